// round 3
// baseline (speedup 1.0000x reference)
#include <cuda_runtime.h>
#include <math.h>

#define S_TOK 4032
#define DIMC  1536
#define NHEAD 12
#define HDIM  128
#define ROTC  64
#define FRAME 448

// Scratch (device globals: no allocation allowed in kernel_launch)
__device__ float g_q[S_TOK * DIMC];
__device__ float g_k[S_TOK * DIMC];
__device__ float g_v[S_TOK * DIMC];
__device__ float g_attn[S_TOK * DIMC];

// ---------------------------------------------------------------------------
// tf32 helpers
// ---------------------------------------------------------------------------
__device__ __forceinline__ unsigned f2tf(float x) {
    unsigned r;
    asm("cvt.rna.tf32.f32 %0, %1;" : "=r"(r) : "f"(x));
    return r;
}
__device__ __forceinline__ void mma_tf32(float* d, const unsigned* a,
                                         unsigned b0, unsigned b1) {
    asm volatile(
        "mma.sync.aligned.m16n8k8.row.col.f32.tf32.tf32.f32 "
        "{%0,%1,%2,%3}, {%4,%5,%6,%7}, {%8,%9}, {%0,%1,%2,%3};\n"
        : "+f"(d[0]), "+f"(d[1]), "+f"(d[2]), "+f"(d[3])
        : "r"(a[0]), "r"(a[1]), "r"(a[2]), "r"(a[3]), "r"(b0), "r"(b1));
}

// ---------------------------------------------------------------------------
// tf32 tensor-core GEMM: C = A[4032,1536] @ B[1536,1536] + bias
// CTA tile 128x128, K-step 32, double-buffered, fragment-order smem.
// 256 threads = 8 warps (2m x 4n), warp tile 64x32.
//
// A-frag smem: [kk(4)][m16(8)][lane(32)][reg(4)]  -> LDS.128 per fragment
// B-frag smem: [kk(4)][n8(16)][lane(32)][reg(2)]  -> LDS.64  per fragment
// ---------------------------------------------------------------------------
#define GEMM_SMEM_U (2 * 4096 + 2 * 4096)   // 64 KB

__device__ __forceinline__ void gemm_tc(const float* __restrict__ A,
                                        const float* __restrict__ B,
                                        const float* __restrict__ bias,
                                        float* __restrict__ C,
                                        int row0, int col0,
                                        unsigned* smu)
{
    unsigned* Af = smu;          // 2 x 4096
    unsigned* Bf = smu + 8192;   // 2 x 4096

    const int tid  = threadIdx.x;
    const int lane = tid & 31;
    const int warp = tid >> 5;
    const int wm = warp >> 2;       // 0..1
    const int wn = warp & 3;        // 0..3

    // A staging: thread loads rows (tid>>3)+32p, k = (tid&7)*4 .. +3
    const int a_row = tid >> 3;             // 0..31
    const int a_k4  = (tid & 7) << 2;       // 0..28
    const int a_kk  = a_k4 >> 3;
    const int a_reg = (((a_k4 & 7) >= 4) ? 2 : 0) + (((a_row & 15) >= 8) ? 1 : 0);
    const int a_m16b = a_row >> 4;          // 0..1
    const int a_lf  = (a_row & 7) * 4;      // + element
    // B staging: thread loads k = (tid>>5)+8p, n = (tid&31)*4 .. +3
    const int b_k   = tid >> 5;             // 0..7
    const int b_n4  = (tid & 31) << 2;      // 0..124
    const int b_n8  = b_n4 >> 3;
    const int b_reg = (b_k >= 4) ? 1 : 0;
    const int b_lf  = (b_n4 & 7) * 4 + (b_k & 3);

    float4 areg[4], breg[4];
    float acc[4][4][4];
#pragma unroll
    for (int mt = 0; mt < 4; mt++)
#pragma unroll
        for (int nt = 0; nt < 4; nt++)
#pragma unroll
            for (int i = 0; i < 4; i++) acc[mt][nt][i] = 0.f;

    auto load_tile = [&](int kb) {
#pragma unroll
        for (int p = 0; p < 4; p++) {
            int row = row0 + p * 32 + a_row;
            row = (row < S_TOK) ? row : (S_TOK - 1);
            areg[p] = *(const float4*)&A[(size_t)row * DIMC + kb + a_k4];
            breg[p] = *(const float4*)&B[(size_t)(kb + p * 8 + b_k) * DIMC + col0 + b_n4];
        }
    };
    auto store_tile = [&](unsigned* Ab, unsigned* Bb) {
#pragma unroll
        for (int p = 0; p < 4; p++) {
            unsigned ab = ((unsigned)(a_kk * 8 + a_m16b + 2 * p) * 32 + a_lf) * 4 + a_reg;
            Ab[ab + 0]  = f2tf(areg[p].x);
            Ab[ab + 4]  = f2tf(areg[p].y);
            Ab[ab + 8]  = f2tf(areg[p].z);
            Ab[ab + 12] = f2tf(areg[p].w);
            unsigned bb = ((unsigned)(p * 16 + b_n8) * 32 + b_lf) * 2 + b_reg;
            Bb[bb + 0]  = f2tf(breg[p].x);
            Bb[bb + 8]  = f2tf(breg[p].y);
            Bb[bb + 16] = f2tf(breg[p].z);
            Bb[bb + 24] = f2tf(breg[p].w);
        }
    };
    auto compute = [&](const unsigned* Ab, const unsigned* Bb) {
#pragma unroll
        for (int kk = 0; kk < 4; kk++) {
            uint4 a[4];
            uint2 b[4];
#pragma unroll
            for (int mt = 0; mt < 4; mt++)
                a[mt] = *(const uint4*)&Ab[((kk * 8 + wm * 4 + mt) * 32 + lane) * 4];
#pragma unroll
            for (int nt = 0; nt < 4; nt++)
                b[nt] = *(const uint2*)&Bb[((kk * 16 + wn * 4 + nt) * 32 + lane) * 2];
#pragma unroll
            for (int mt = 0; mt < 4; mt++)
#pragma unroll
                for (int nt = 0; nt < 4; nt++)
                    mma_tf32(acc[mt][nt], (const unsigned*)&a[mt], b[nt].x, b[nt].y);
        }
    };

    load_tile(0);
    store_tile(Af, Bf);
    __syncthreads();
    const int NKB = DIMC / 32;   // 48
    for (int kb = 0; kb < NKB; kb++) {
        int cur = kb & 1;
        if (kb < NKB - 1) load_tile((kb + 1) * 32);
        compute(Af + cur * 4096, Bf + cur * 4096);
        if (kb < NKB - 1) {
            store_tile(Af + (cur ^ 1) * 4096, Bf + (cur ^ 1) * 4096);
            __syncthreads();
        }
    }

    // Epilogue
    const int r = lane >> 2, c = lane & 3;
#pragma unroll
    for (int mt = 0; mt < 4; mt++) {
        int row_a = row0 + wm * 64 + mt * 16 + r;
        int row_b = row_a + 8;
#pragma unroll
        for (int nt = 0; nt < 4; nt++) {
            int col = col0 + wn * 32 + nt * 8 + 2 * c;
            float b0 = bias[col], b1 = bias[col + 1];
            if (row_a < S_TOK)
                *(float2*)&C[(size_t)row_a * DIMC + col] =
                    make_float2(acc[mt][nt][0] + b0, acc[mt][nt][1] + b1);
            if (row_b < S_TOK)
                *(float2*)&C[(size_t)row_b * DIMC + col] =
                    make_float2(acc[mt][nt][2] + b0, acc[mt][nt][3] + b1);
        }
    }
}

__global__ void __launch_bounds__(256)
qkv_gemm(const float* __restrict__ x,
         const float* __restrict__ Wq, const float* __restrict__ bq,
         const float* __restrict__ Wk, const float* __restrict__ bk,
         const float* __restrict__ Wv, const float* __restrict__ bv)
{
    extern __shared__ unsigned smu[];
    int z = blockIdx.z;
    const float* B    = (z == 0) ? Wq : ((z == 1) ? Wk : Wv);
    const float* bias = (z == 0) ? bq : ((z == 1) ? bk : bv);
    float* C          = (z == 0) ? g_q : ((z == 1) ? g_k : g_v);
    gemm_tc(x, B, bias, C, blockIdx.y * 128, blockIdx.x * 128, smu);
}

__global__ void __launch_bounds__(256)
out_gemm(const float* __restrict__ Wo, const float* __restrict__ bo,
         float* __restrict__ out)
{
    extern __shared__ unsigned smu[];
    gemm_tc(g_attn, Wo, bo, out, blockIdx.y * 128, blockIdx.x * 128, smu);
}

// ---------------------------------------------------------------------------
// Fused RMSNorm (full DIM) + 3D RoPE, in-place on g_q / g_k. 1 block/token.
// ---------------------------------------------------------------------------
__global__ void norm_rope_kernel(const float* __restrict__ freqs,
                                 const float* __restrict__ gq,
                                 const float* __restrict__ gk)
{
    int s = blockIdx.x;
    int tid = threadIdx.x;
    float* qrow = g_q + (size_t)s * DIMC;
    float* krow = g_k + (size_t)s * DIMC;

    float2 qv[3], kv[3];
    float sq = 0.f, sk = 0.f;
#pragma unroll
    for (int p = 0; p < 3; p++) {
        int pr = tid + p * 256;
        qv[p] = *(const float2*)&qrow[2 * pr];
        kv[p] = *(const float2*)&krow[2 * pr];
        sq += qv[p].x * qv[p].x + qv[p].y * qv[p].y;
        sk += kv[p].x * kv[p].x + kv[p].y * kv[p].y;
    }
    __shared__ float red[2][8];
#pragma unroll
    for (int o = 16; o > 0; o >>= 1) {
        sq += __shfl_down_sync(0xffffffffu, sq, o);
        sk += __shfl_down_sync(0xffffffffu, sk, o);
    }
    int warp = tid >> 5;
    if ((tid & 31) == 0) { red[0][warp] = sq; red[1][warp] = sk; }
    __syncthreads();
    sq = 0.f; sk = 0.f;
#pragma unroll
    for (int w = 0; w < 8; w++) { sq += red[0][w]; sk += red[1][w]; }
    float rq = rsqrtf(sq * (1.f / DIMC) + 1e-6f);
    float rk = rsqrtf(sk * (1.f / DIMC) + 1e-6f);

    int f = s / FRAME;
    int rem = s % FRAME;
    int hh = rem / 28;
    int ww = rem % 28;
#pragma unroll
    for (int p = 0; p < 3; p++) {
        int pr = tid + p * 256;
        int rot = pr & 63;
        float a;
        if (rot < 22)       a = freqs[f  * ROTC + rot];
        else if (rot < 43)  a = freqs[hh * ROTC + rot];
        else                a = freqs[ww * ROTC + rot];
        float cc = cosf(a), sn = sinf(a);
        float q0 = qv[p].x * rq * gq[2 * pr];
        float q1 = qv[p].y * rq * gq[2 * pr + 1];
        float k0 = kv[p].x * rk * gk[2 * pr];
        float k1 = kv[p].y * rk * gk[2 * pr + 1];
        *(float2*)&qrow[2 * pr] = make_float2(q0 * cc - q1 * sn, q0 * sn + q1 * cc);
        *(float2*)&krow[2 * pr] = make_float2(k0 * cc - k1 * sn, k0 * sn + k1 * cc);
    }
}

// ---------------------------------------------------------------------------
// Frame-causal flash attention, tf32 tensor cores, fragment-order K/V smem.
// Block = (64 q-rows, head), 128 threads (4 warps, 16 q-rows each).
//
// Qs: [64][132] raw layout (Q frags pulled to regs once); aliased by Ps[64][68]
// Kf: [dt(16)][n8(8)][lane(32)][reg(2)]   (B-op of Q K^T, k-dim = d)
// Vf: [k8(8)][n8(16)][lane(32)][reg(2)]   (B-op of P V,  k-dim = key)
// ---------------------------------------------------------------------------
#define KF_OFF (64 * 132)
#define VF_OFF (KF_OFF + 8192)
#define ATTN_SMEM_U (VF_OFF + 8192)
#define PS_STRIDE 68

__global__ void __launch_bounds__(128)
attn_kernel()
{
    extern __shared__ unsigned smu[];
    unsigned* Qs = smu;
    unsigned* Ps = smu;           // alias (Qs dead after frag load)
    unsigned* Kf = smu + KF_OFF;
    unsigned* Vf = smu + VF_OFF;

    const int tid  = threadIdx.x;
    const int lane = tid & 31;
    const int w    = tid >> 5;
    const int r    = lane >> 2;
    const int c    = lane & 3;
    const int w16  = w * 16;

    const int row0 = blockIdx.x * 64;
    const int h    = blockIdx.y;
    const int ktiles = (row0 / FRAME + 1) * (FRAME / 64);
    const float scale = 0.08838834764831845f;   // 1/sqrt(128)

    // Stage Q (scale folded), raw row layout
#pragma unroll
    for (int it = 0; it < 16; it++) {
        int idx = tid + it * 128;
        int rr = idx >> 5;
        int cc = (idx & 31) << 2;
        float4 v = *(const float4*)&g_q[(size_t)(row0 + rr) * DIMC + h * HDIM + cc];
        Qs[rr * 132 + cc + 0] = f2tf(v.x * scale);
        Qs[rr * 132 + cc + 1] = f2tf(v.y * scale);
        Qs[rr * 132 + cc + 2] = f2tf(v.z * scale);
        Qs[rr * 132 + cc + 3] = f2tf(v.w * scale);
    }
    __syncthreads();

    // Q fragments -> registers for whole block
    unsigned qa[16][4];
#pragma unroll
    for (int dt = 0; dt < 16; dt++) {
        qa[dt][0] = Qs[(w16 + r) * 132 + dt * 8 + c];
        qa[dt][1] = Qs[(w16 + r + 8) * 132 + dt * 8 + c];
        qa[dt][2] = Qs[(w16 + r) * 132 + dt * 8 + c + 4];
        qa[dt][3] = Qs[(w16 + r + 8) * 132 + dt * 8 + c + 4];
    }

    float O[16][4];
#pragma unroll
    for (int nt = 0; nt < 16; nt++)
#pragma unroll
        for (int i = 0; i < 4; i++) O[nt][i] = 0.f;
    float m0 = -1e30f, m1 = -1e30f, l0 = 0.f, l1 = 0.f;

    for (int kt = 0; kt < ktiles; kt++) {
        int krow0 = kt * 64;
        __syncthreads();   // Kf/Vf overwrite vs previous readers
        // Stage K, V in fragment order (tf32)
#pragma unroll
        for (int it = 0; it < 16; it++) {
            int idx = tid + it * 128;
            int key = idx >> 5;                 // 0..63
            int d4  = (idx & 31) << 2;          // 0..124
            float4 kv = *(const float4*)&g_k[(size_t)(krow0 + key) * DIMC + h * HDIM + d4];
            {
                int kk  = d4 >> 3;
                int reg = ((d4 & 7) >= 4) ? 1 : 0;
                unsigned base = ((unsigned)(kk * 8 + (key >> 3)) * 32 + (key & 7) * 4) * 2 + reg;
                Kf[base + 0] = f2tf(kv.x);
                Kf[base + 2] = f2tf(kv.y);
                Kf[base + 4] = f2tf(kv.z);
                Kf[base + 6] = f2tf(kv.w);
            }
            float4 vv = *(const float4*)&g_v[(size_t)(krow0 + key) * DIMC + h * HDIM + d4];
            {
                int k8  = key >> 3;
                int reg = ((key & 7) >= 4) ? 1 : 0;
                unsigned base = ((unsigned)(k8 * 16 + (d4 >> 3)) * 32
                                 + (d4 & 7) * 4 + (key & 3)) * 2 + reg;
                Vf[base + 0]  = f2tf(vv.x);
                Vf[base + 8]  = f2tf(vv.y);
                Vf[base + 16] = f2tf(vv.z);
                Vf[base + 24] = f2tf(vv.w);
            }
        }
        __syncthreads();

        // S = Q K^T  (warp's 16 q-rows x 64 keys)
        float S[8][4];
#pragma unroll
        for (int nt = 0; nt < 8; nt++)
#pragma unroll
            for (int i = 0; i < 4; i++) S[nt][i] = 0.f;
#pragma unroll
        for (int dt = 0; dt < 16; dt++) {
#pragma unroll
            for (int nt = 0; nt < 8; nt++) {
                uint2 b = *(const uint2*)&Kf[((dt * 8 + nt) * 32 + lane) * 2];
                mma_tf32(S[nt], qa[dt], b.x, b.y);
            }
        }

        // Online softmax (rows r and r+8 of warp band)
        float mx0 = -1e30f, mx1 = -1e30f;
#pragma unroll
        for (int nt = 0; nt < 8; nt++) {
            mx0 = fmaxf(mx0, fmaxf(S[nt][0], S[nt][1]));
            mx1 = fmaxf(mx1, fmaxf(S[nt][2], S[nt][3]));
        }
        mx0 = fmaxf(mx0, __shfl_xor_sync(0xffffffffu, mx0, 1));
        mx0 = fmaxf(mx0, __shfl_xor_sync(0xffffffffu, mx0, 2));
        mx1 = fmaxf(mx1, __shfl_xor_sync(0xffffffffu, mx1, 1));
        mx1 = fmaxf(mx1, __shfl_xor_sync(0xffffffffu, mx1, 2));
        float mn0 = fmaxf(m0, mx0), mn1 = fmaxf(m1, mx1);
        float fac0 = __expf(m0 - mn0), fac1 = __expf(m1 - mn1);

        __syncwarp();
        float sum0 = 0.f, sum1 = 0.f;
#pragma unroll
        for (int nt = 0; nt < 8; nt++) {
            float p00 = __expf(S[nt][0] - mn0);
            float p01 = __expf(S[nt][1] - mn0);
            float p10 = __expf(S[nt][2] - mn1);
            float p11 = __expf(S[nt][3] - mn1);
            sum0 += p00 + p01;
            sum1 += p10 + p11;
            *(uint2*)&Ps[(w16 + r) * PS_STRIDE + nt * 8 + 2 * c] =
                make_uint2(f2tf(p00), f2tf(p01));
            *(uint2*)&Ps[(w16 + r + 8) * PS_STRIDE + nt * 8 + 2 * c] =
                make_uint2(f2tf(p10), f2tf(p11));
        }
        sum0 += __shfl_xor_sync(0xffffffffu, sum0, 1);
        sum0 += __shfl_xor_sync(0xffffffffu, sum0, 2);
        sum1 += __shfl_xor_sync(0xffffffffu, sum1, 1);
        sum1 += __shfl_xor_sync(0xffffffffu, sum1, 2);
        l0 = l0 * fac0 + sum0;
        l1 = l1 * fac1 + sum1;
        m0 = mn0; m1 = mn1;

#pragma unroll
        for (int nt = 0; nt < 16; nt++) {
            O[nt][0] *= fac0; O[nt][1] *= fac0;
            O[nt][2] *= fac1; O[nt][3] *= fac1;
        }
        __syncwarp();

        // O += P V
#pragma unroll
        for (int k8 = 0; k8 < 8; k8++) {
            unsigned pa[4];
            pa[0] = Ps[(w16 + r) * PS_STRIDE + k8 * 8 + c];
            pa[1] = Ps[(w16 + r + 8) * PS_STRIDE + k8 * 8 + c];
            pa[2] = Ps[(w16 + r) * PS_STRIDE + k8 * 8 + c + 4];
            pa[3] = Ps[(w16 + r + 8) * PS_STRIDE + k8 * 8 + c + 4];
#pragma unroll
            for (int nt = 0; nt < 16; nt++) {
                uint2 b = *(const uint2*)&Vf[((k8 * 16 + nt) * 32 + lane) * 2];
                mma_tf32(O[nt], pa, b.x, b.y);
            }
        }
    }

    // Epilogue: normalize, write [S, H*D]
    float inv0 = 1.f / l0, inv1 = 1.f / l1;
    int row_a = row0 + w16 + r;
    int row_b = row_a + 8;
#pragma unroll
    for (int nt = 0; nt < 16; nt++) {
        int col = h * HDIM + nt * 8 + 2 * c;
        *(float2*)&g_attn[(size_t)row_a * DIMC + col] =
            make_float2(O[nt][0] * inv0, O[nt][1] * inv0);
        *(float2*)&g_attn[(size_t)row_b * DIMC + col] =
            make_float2(O[nt][2] * inv1, O[nt][3] * inv1);
    }
}

// ---------------------------------------------------------------------------
extern "C" void kernel_launch(void* const* d_in, const int* in_sizes, int n_in,
                              void* d_out, int out_size)
{
    (void)in_sizes; (void)n_in; (void)out_size;
    const float* x     = (const float*)d_in[0];
    const float* freqs = (const float*)d_in[3];
    const float* Wq    = (const float*)d_in[4];
    const float* bq    = (const float*)d_in[5];
    const float* Wk    = (const float*)d_in[6];
    const float* bk    = (const float*)d_in[7];
    const float* Wv    = (const float*)d_in[8];
    const float* bv    = (const float*)d_in[9];
    const float* Wo    = (const float*)d_in[10];
    const float* bo    = (const float*)d_in[11];
    const float* gq    = (const float*)d_in[12];
    const float* gk    = (const float*)d_in[13];
    float* out = (float*)d_out;

    const int gemm_smem = GEMM_SMEM_U * 4;   // 65,536 B
    const int attn_smem = ATTN_SMEM_U * 4;   // 99,328 B
    cudaFuncSetAttribute(qkv_gemm,
                         cudaFuncAttributeMaxDynamicSharedMemorySize, gemm_smem);
    cudaFuncSetAttribute(out_gemm,
                         cudaFuncAttributeMaxDynamicSharedMemorySize, gemm_smem);
    cudaFuncSetAttribute(attn_kernel,
                         cudaFuncAttributeMaxDynamicSharedMemorySize, attn_smem);

    qkv_gemm<<<dim3(12, 32, 3), 256, gemm_smem>>>(x, Wq, bq, Wk, bk, Wv, bv);
    norm_rope_kernel<<<S_TOK, 256>>>(freqs, gq, gk);
    attn_kernel<<<dim3(63, 12), 128, attn_smem>>>();
    out_gemm<<<dim3(12, 32), 256, gemm_smem>>>(Wo, bo, out);
}

// round 4
// speedup vs baseline: 2.5283x; 2.5283x over previous
#include <cuda_runtime.h>
#include <math.h>

#define S_TOK 4032
#define DIMC  1536
#define NHEAD 12
#define HDIM  128
#define ROTC  64
#define FRAME 448

// Scratch (device globals: no allocation allowed in kernel_launch)
__device__ float g_q[S_TOK * DIMC];
__device__ float g_k[S_TOK * DIMC];
__device__ float g_v[S_TOK * DIMC];
__device__ float g_attn[S_TOK * DIMC];

// ---------------------------------------------------------------------------
// tf32 / async helpers
// ---------------------------------------------------------------------------
__device__ __forceinline__ unsigned f2tf(float x) {
    unsigned r;
    asm("cvt.rna.tf32.f32 %0, %1;" : "=r"(r) : "f"(x));
    return r;
}
__device__ __forceinline__ unsigned u2tf(unsigned x) {
    unsigned r;
    asm("cvt.rna.tf32.f32 %0, %1;" : "=r"(r) : "f"(__uint_as_float(x)));
    return r;
}
__device__ __forceinline__ void mma_tf32(float* d, const unsigned* a,
                                         unsigned b0, unsigned b1) {
    asm volatile(
        "mma.sync.aligned.m16n8k8.row.col.f32.tf32.tf32.f32 "
        "{%0,%1,%2,%3}, {%4,%5,%6,%7}, {%8,%9}, {%0,%1,%2,%3};\n"
        : "+f"(d[0]), "+f"(d[1]), "+f"(d[2]), "+f"(d[3])
        : "r"(a[0]), "r"(a[1]), "r"(a[2]), "r"(a[3]), "r"(b0), "r"(b1));
}
__device__ __forceinline__ void ldsm_x4(uint4& d, unsigned addr) {
    asm volatile("ldmatrix.sync.aligned.m8n8.x4.shared.b16 {%0,%1,%2,%3}, [%4];"
                 : "=r"(d.x), "=r"(d.y), "=r"(d.z), "=r"(d.w) : "r"(addr));
}
#define CP16(dst, src) \
    asm volatile("cp.async.cg.shared.global [%0], [%1], 16;" :: "r"(dst), "l"(src))
#define CP_COMMIT() asm volatile("cp.async.commit_group;")
#define CP_WAIT(n)  asm volatile("cp.async.wait_group %0;" :: "n"(n))

// ---------------------------------------------------------------------------
// tf32 tensor-core GEMM: C = A[4032,1536] @ B[1536,1536] + bias
// CTA 128x128, K-step 32, cp.async double-buffered, ldmatrix A-frags.
// 256 threads = 8 warps (2m x 4n), warp tile 64x32.
// As: [m(128)][k(32)+4pad]  raw fp32 (stride 36 words)
// Bs: [k(32)][n(128)+4pad]  raw fp32 (stride 132 words)
// ---------------------------------------------------------------------------
#define AS_W 36
#define BS_W 132
#define A_WORDS (128 * AS_W)          // 4608
#define B_WORDS (32 * BS_W)           // 4224
#define BUF_WORDS (A_WORDS + B_WORDS) // 8832
#define GEMM_SMEM_BYTES (2 * BUF_WORDS * 4)   // 70,656

__device__ __forceinline__ void gemm_tc(const float* __restrict__ A,
                                        const float* __restrict__ B,
                                        const float* __restrict__ bias,
                                        float* __restrict__ C,
                                        int row0, int col0,
                                        unsigned* smu)
{
    const int tid  = threadIdx.x;
    const int lane = tid & 31;
    const int warp = tid >> 5;
    const int wm = warp >> 2;       // 0..1
    const int wn = warp & 3;        // 0..3
    const int r  = lane >> 2;       // 0..7
    const int c  = lane & 3;        // 0..3

    // ldmatrix lane address components
    const int a_lrow  = lane & 15;          // row within 16-row tile
    const int a_lhalf = (lane >> 4) << 2;   // 0 or 4 (k-word half)

    // staging coords
    const int st_arow = tid >> 3;           // 0..31 base (x4 passes of 32 rows)
    const int st_ak   = (tid & 7) << 2;     // 0..28
    const int st_bk   = tid >> 5;           // 0..7 base (x4 passes of 8 k)
    const int st_bn   = (tid & 31) << 2;    // 0..124

    float acc[4][4][4];
#pragma unroll
    for (int mt = 0; mt < 4; mt++)
#pragma unroll
        for (int nt = 0; nt < 4; nt++)
#pragma unroll
            for (int i = 0; i < 4; i++) acc[mt][nt][i] = 0.f;

    auto issue_tile = [&](int kb, int buf) {
        unsigned abase = (unsigned)__cvta_generic_to_shared(&smu[buf * BUF_WORDS]);
        unsigned bbase = (unsigned)__cvta_generic_to_shared(&smu[buf * BUF_WORDS + A_WORDS]);
#pragma unroll
        for (int p = 0; p < 4; p++) {
            int row  = st_arow + p * 32;
            int grow = row0 + row;
            grow = (grow < S_TOK) ? grow : (S_TOK - 1);
            CP16(abase + (unsigned)(row * AS_W + st_ak) * 4,
                 &A[(size_t)grow * DIMC + kb + st_ak]);
            int kr = st_bk + p * 8;
            CP16(bbase + (unsigned)(kr * BS_W + st_bn) * 4,
                 &B[(size_t)(kb + kr) * DIMC + col0 + st_bn]);
        }
    };

    auto compute = [&](int buf) {
        const unsigned* As = smu + buf * BUF_WORDS;
        const unsigned* Bs = smu + buf * BUF_WORDS + A_WORDS;
#pragma unroll
        for (int kk = 0; kk < 4; kk++) {
            uint4 a[4];
#pragma unroll
            for (int mt = 0; mt < 4; mt++) {
                unsigned addr = (unsigned)__cvta_generic_to_shared(
                    &As[(wm * 64 + mt * 16 + a_lrow) * AS_W + kk * 8 + a_lhalf]);
                ldsm_x4(a[mt], addr);
                a[mt].x = u2tf(a[mt].x);
                a[mt].y = u2tf(a[mt].y);
                a[mt].z = u2tf(a[mt].z);
                a[mt].w = u2tf(a[mt].w);
            }
            uint2 b[4];
#pragma unroll
            for (int nt = 0; nt < 4; nt++) {
                int nb = wn * 32 + nt * 8 + r;
                b[nt].x = u2tf(Bs[(kk * 8 + c) * BS_W + nb]);
                b[nt].y = u2tf(Bs[(kk * 8 + c + 4) * BS_W + nb]);
            }
#pragma unroll
            for (int mt = 0; mt < 4; mt++)
#pragma unroll
                for (int nt = 0; nt < 4; nt++)
                    mma_tf32(acc[mt][nt], (const unsigned*)&a[mt], b[nt].x, b[nt].y);
        }
    };

    issue_tile(0, 0);
    CP_COMMIT();
    const int NKB = DIMC / 32;   // 48
    for (int kb = 0; kb < NKB; kb++) {
        int cur = kb & 1;
        if (kb < NKB - 1) {
            issue_tile((kb + 1) * 32, cur ^ 1);
            CP_COMMIT();
            CP_WAIT(1);
        } else {
            CP_WAIT(0);
        }
        __syncthreads();
        compute(cur);
        __syncthreads();
    }

    // Epilogue
#pragma unroll
    for (int mt = 0; mt < 4; mt++) {
        int row_a = row0 + wm * 64 + mt * 16 + r;
        int row_b = row_a + 8;
#pragma unroll
        for (int nt = 0; nt < 4; nt++) {
            int col = col0 + wn * 32 + nt * 8 + 2 * c;
            float b0 = bias[col], b1 = bias[col + 1];
            if (row_a < S_TOK)
                *(float2*)&C[(size_t)row_a * DIMC + col] =
                    make_float2(acc[mt][nt][0] + b0, acc[mt][nt][1] + b1);
            if (row_b < S_TOK)
                *(float2*)&C[(size_t)row_b * DIMC + col] =
                    make_float2(acc[mt][nt][2] + b0, acc[mt][nt][3] + b1);
        }
    }
}

__global__ void __launch_bounds__(256)
qkv_gemm(const float* __restrict__ x,
         const float* __restrict__ Wq, const float* __restrict__ bq,
         const float* __restrict__ Wk, const float* __restrict__ bk,
         const float* __restrict__ Wv, const float* __restrict__ bv)
{
    extern __shared__ unsigned smu[];
    int z = blockIdx.z;
    const float* B    = (z == 0) ? Wq : ((z == 1) ? Wk : Wv);
    const float* bias = (z == 0) ? bq : ((z == 1) ? bk : bv);
    float* C          = (z == 0) ? g_q : ((z == 1) ? g_k : g_v);
    gemm_tc(x, B, bias, C, blockIdx.y * 128, blockIdx.x * 128, smu);
}

__global__ void __launch_bounds__(256)
out_gemm(const float* __restrict__ Wo, const float* __restrict__ bo,
         float* __restrict__ out)
{
    extern __shared__ unsigned smu[];
    gemm_tc(g_attn, Wo, bo, out, blockIdx.y * 128, blockIdx.x * 128, smu);
}

// ---------------------------------------------------------------------------
// Fused RMSNorm (full DIM) + 3D RoPE, in-place on g_q / g_k. 1 block/token.
// (round-2 verbatim)
// ---------------------------------------------------------------------------
__global__ void norm_rope_kernel(const float* __restrict__ freqs,
                                 const float* __restrict__ gq,
                                 const float* __restrict__ gk)
{
    int s = blockIdx.x;
    int tid = threadIdx.x;
    float* qrow = g_q + (size_t)s * DIMC;
    float* krow = g_k + (size_t)s * DIMC;

    float2 qv[3], kv[3];
    float sq = 0.f, sk = 0.f;
#pragma unroll
    for (int p = 0; p < 3; p++) {
        int pr = tid + p * 256;
        qv[p] = *(const float2*)&qrow[2 * pr];
        kv[p] = *(const float2*)&krow[2 * pr];
        sq += qv[p].x * qv[p].x + qv[p].y * qv[p].y;
        sk += kv[p].x * kv[p].x + kv[p].y * kv[p].y;
    }
    __shared__ float red[2][8];
#pragma unroll
    for (int o = 16; o > 0; o >>= 1) {
        sq += __shfl_down_sync(0xffffffffu, sq, o);
        sk += __shfl_down_sync(0xffffffffu, sk, o);
    }
    int warp = tid >> 5;
    if ((tid & 31) == 0) { red[0][warp] = sq; red[1][warp] = sk; }
    __syncthreads();
    sq = 0.f; sk = 0.f;
#pragma unroll
    for (int w = 0; w < 8; w++) { sq += red[0][w]; sk += red[1][w]; }
    float rq = rsqrtf(sq * (1.f / DIMC) + 1e-6f);
    float rk = rsqrtf(sk * (1.f / DIMC) + 1e-6f);

    int f = s / FRAME;
    int rem = s % FRAME;
    int hh = rem / 28;
    int ww = rem % 28;
#pragma unroll
    for (int p = 0; p < 3; p++) {
        int pr = tid + p * 256;
        int rot = pr & 63;
        float a;
        if (rot < 22)       a = freqs[f  * ROTC + rot];
        else if (rot < 43)  a = freqs[hh * ROTC + rot];
        else                a = freqs[ww * ROTC + rot];
        float cc = cosf(a), sn = sinf(a);
        float q0 = qv[p].x * rq * gq[2 * pr];
        float q1 = qv[p].y * rq * gq[2 * pr + 1];
        float k0 = kv[p].x * rk * gk[2 * pr];
        float k1 = kv[p].y * rk * gk[2 * pr + 1];
        *(float2*)&qrow[2 * pr] = make_float2(q0 * cc - q1 * sn, q0 * sn + q1 * cc);
        *(float2*)&krow[2 * pr] = make_float2(k0 * cc - k1 * sn, k0 * sn + k1 * cc);
    }
}

// ---------------------------------------------------------------------------
// Frame-causal flash attention, tf32 tensor cores. (round-2 verbatim)
// Block = (64 q-rows, head), 128 threads (4 warps, 16 q-rows each).
// ---------------------------------------------------------------------------
#define QS_OFF 0
#define KS_OFF (64 * 132)
#define VS_OFF (128 * 132)
#define ATTN_SMEM_U (192 * 132)
#define PS_STRIDE 68

__global__ void __launch_bounds__(128)
attn_kernel()
{
    extern __shared__ unsigned asm_u[];
    unsigned* Qs = asm_u + QS_OFF;
    unsigned* Ps = asm_u + QS_OFF;    // alias (Qs dead after frag load)
    unsigned* Ks = asm_u + KS_OFF;
    unsigned* Vs = asm_u + VS_OFF;

    const int tid  = threadIdx.x;
    const int lane = tid & 31;
    const int w    = tid >> 5;
    const int r    = lane >> 2;
    const int c    = lane & 3;
    const int w16  = w * 16;

    const int row0 = blockIdx.x * 64;
    const int h    = blockIdx.y;
    const int ktiles = (row0 / FRAME + 1) * (FRAME / 64);
    const float scale = 0.08838834764831845f;   // 1/sqrt(128)

#pragma unroll
    for (int it = 0; it < 16; it++) {
        int idx = tid + it * 128;
        int rr = idx >> 5;
        int cc = (idx & 31) << 2;
        float4 v = *(const float4*)&g_q[(size_t)(row0 + rr) * DIMC + h * HDIM + cc];
        Qs[rr * 132 + cc + 0] = f2tf(v.x * scale);
        Qs[rr * 132 + cc + 1] = f2tf(v.y * scale);
        Qs[rr * 132 + cc + 2] = f2tf(v.z * scale);
        Qs[rr * 132 + cc + 3] = f2tf(v.w * scale);
    }
    __syncthreads();

    unsigned qa[16][4];
#pragma unroll
    for (int dt = 0; dt < 16; dt++) {
        qa[dt][0] = Qs[(w16 + r) * 132 + dt * 8 + c];
        qa[dt][1] = Qs[(w16 + r + 8) * 132 + dt * 8 + c];
        qa[dt][2] = Qs[(w16 + r) * 132 + dt * 8 + c + 4];
        qa[dt][3] = Qs[(w16 + r + 8) * 132 + dt * 8 + c + 4];
    }

    float O[16][4];
#pragma unroll
    for (int nt = 0; nt < 16; nt++)
#pragma unroll
        for (int i = 0; i < 4; i++) O[nt][i] = 0.f;
    float m0 = -1e30f, m1 = -1e30f, l0 = 0.f, l1 = 0.f;

    for (int kt = 0; kt < ktiles; kt++) {
        int krow0 = kt * 64;
        __syncthreads();
#pragma unroll
        for (int it = 0; it < 16; it++) {
            int idx = tid + it * 128;
            int rr = idx >> 5;
            int cc = (idx & 31) << 2;
            float4 kv = *(const float4*)&g_k[(size_t)(krow0 + rr) * DIMC + h * HDIM + cc];
            Ks[rr * 132 + cc + 0] = f2tf(kv.x);
            Ks[rr * 132 + cc + 1] = f2tf(kv.y);
            Ks[rr * 132 + cc + 2] = f2tf(kv.z);
            Ks[rr * 132 + cc + 3] = f2tf(kv.w);
            float4 vv = *(const float4*)&g_v[(size_t)(krow0 + rr) * DIMC + h * HDIM + cc];
            Vs[rr * 132 + cc + 0] = f2tf(vv.x);
            Vs[rr * 132 + cc + 1] = f2tf(vv.y);
            Vs[rr * 132 + cc + 2] = f2tf(vv.z);
            Vs[rr * 132 + cc + 3] = f2tf(vv.w);
        }
        __syncthreads();

        float S[8][4];
#pragma unroll
        for (int nt = 0; nt < 8; nt++)
#pragma unroll
            for (int i = 0; i < 4; i++) S[nt][i] = 0.f;
#pragma unroll
        for (int dt = 0; dt < 16; dt++) {
#pragma unroll
            for (int nt = 0; nt < 8; nt++) {
                unsigned b0 = Ks[(nt * 8 + r) * 132 + dt * 8 + c];
                unsigned b1 = Ks[(nt * 8 + r) * 132 + dt * 8 + c + 4];
                mma_tf32(S[nt], qa[dt], b0, b1);
            }
        }

        float mx0 = -1e30f, mx1 = -1e30f;
#pragma unroll
        for (int nt = 0; nt < 8; nt++) {
            mx0 = fmaxf(mx0, fmaxf(S[nt][0], S[nt][1]));
            mx1 = fmaxf(mx1, fmaxf(S[nt][2], S[nt][3]));
        }
        mx0 = fmaxf(mx0, __shfl_xor_sync(0xffffffffu, mx0, 1));
        mx0 = fmaxf(mx0, __shfl_xor_sync(0xffffffffu, mx0, 2));
        mx1 = fmaxf(mx1, __shfl_xor_sync(0xffffffffu, mx1, 1));
        mx1 = fmaxf(mx1, __shfl_xor_sync(0xffffffffu, mx1, 2));
        float mn0 = fmaxf(m0, mx0), mn1 = fmaxf(m1, mx1);
        float fac0 = __expf(m0 - mn0), fac1 = __expf(m1 - mn1);

        __syncwarp();
        float sum0 = 0.f, sum1 = 0.f;
#pragma unroll
        for (int nt = 0; nt < 8; nt++) {
            float p00 = __expf(S[nt][0] - mn0);
            float p01 = __expf(S[nt][1] - mn0);
            float p10 = __expf(S[nt][2] - mn1);
            float p11 = __expf(S[nt][3] - mn1);
            sum0 += p00 + p01;
            sum1 += p10 + p11;
            *(uint2*)&Ps[(w16 + r) * PS_STRIDE + nt * 8 + 2 * c] =
                make_uint2(f2tf(p00), f2tf(p01));
            *(uint2*)&Ps[(w16 + r + 8) * PS_STRIDE + nt * 8 + 2 * c] =
                make_uint2(f2tf(p10), f2tf(p11));
        }
        sum0 += __shfl_xor_sync(0xffffffffu, sum0, 1);
        sum0 += __shfl_xor_sync(0xffffffffu, sum0, 2);
        sum1 += __shfl_xor_sync(0xffffffffu, sum1, 1);
        sum1 += __shfl_xor_sync(0xffffffffu, sum1, 2);
        l0 = l0 * fac0 + sum0;
        l1 = l1 * fac1 + sum1;
        m0 = mn0; m1 = mn1;

#pragma unroll
        for (int nt = 0; nt < 16; nt++) {
            O[nt][0] *= fac0; O[nt][1] *= fac0;
            O[nt][2] *= fac1; O[nt][3] *= fac1;
        }
        __syncwarp();

#pragma unroll
        for (int k8 = 0; k8 < 8; k8++) {
            unsigned pa[4];
            pa[0] = Ps[(w16 + r) * PS_STRIDE + k8 * 8 + c];
            pa[1] = Ps[(w16 + r + 8) * PS_STRIDE + k8 * 8 + c];
            pa[2] = Ps[(w16 + r) * PS_STRIDE + k8 * 8 + c + 4];
            pa[3] = Ps[(w16 + r + 8) * PS_STRIDE + k8 * 8 + c + 4];
#pragma unroll
            for (int nt = 0; nt < 16; nt++) {
                unsigned b0 = Vs[(k8 * 8 + c) * 132 + nt * 8 + r];
                unsigned b1 = Vs[(k8 * 8 + c + 4) * 132 + nt * 8 + r];
                mma_tf32(O[nt], pa, b0, b1);
            }
        }
    }

    float inv0 = 1.f / l0, inv1 = 1.f / l1;
    int row_a = row0 + w16 + r;
    int row_b = row_a + 8;
#pragma unroll
    for (int nt = 0; nt < 16; nt++) {
        int col = h * HDIM + nt * 8 + 2 * c;
        *(float2*)&g_attn[(size_t)row_a * DIMC + col] =
            make_float2(O[nt][0] * inv0, O[nt][1] * inv0);
        *(float2*)&g_attn[(size_t)row_b * DIMC + col] =
            make_float2(O[nt][2] * inv1, O[nt][3] * inv1);
    }
}

// ---------------------------------------------------------------------------
extern "C" void kernel_launch(void* const* d_in, const int* in_sizes, int n_in,
                              void* d_out, int out_size)
{
    (void)in_sizes; (void)n_in; (void)out_size;
    const float* x     = (const float*)d_in[0];
    const float* freqs = (const float*)d_in[3];
    const float* Wq    = (const float*)d_in[4];
    const float* bq    = (const float*)d_in[5];
    const float* Wk    = (const float*)d_in[6];
    const float* bk    = (const float*)d_in[7];
    const float* Wv    = (const float*)d_in[8];
    const float* bv    = (const float*)d_in[9];
    const float* Wo    = (const float*)d_in[10];
    const float* bo    = (const float*)d_in[11];
    const float* gq    = (const float*)d_in[12];
    const float* gk    = (const float*)d_in[13];
    float* out = (float*)d_out;

    const int gemm_smem = GEMM_SMEM_BYTES;   // 70,656 B
    const int attn_smem = ATTN_SMEM_U * 4;   // 101,376 B
    cudaFuncSetAttribute(qkv_gemm,
                         cudaFuncAttributeMaxDynamicSharedMemorySize, gemm_smem);
    cudaFuncSetAttribute(out_gemm,
                         cudaFuncAttributeMaxDynamicSharedMemorySize, gemm_smem);
    cudaFuncSetAttribute(attn_kernel,
                         cudaFuncAttributeMaxDynamicSharedMemorySize, attn_smem);

    qkv_gemm<<<dim3(12, 32, 3), 256, gemm_smem>>>(x, Wq, bq, Wk, bk, Wv, bv);
    norm_rope_kernel<<<S_TOK, 256>>>(freqs, gq, gk);
    attn_kernel<<<dim3(63, 12), 128, attn_smem>>>();
    out_gemm<<<dim3(12, 32), 256, gemm_smem>>>(Wo, bo, out);
}

// round 5
// speedup vs baseline: 2.6311x; 1.0407x over previous
#include <cuda_runtime.h>
#include <math.h>

#define S_TOK 4032
#define DIMC  1536
#define NHEAD 12
#define HDIM  128
#define ROTC  64
#define FRAME 448

// Scratch (device globals: no allocation allowed in kernel_launch)
__device__ float g_q[S_TOK * DIMC];
__device__ float g_k[S_TOK * DIMC];
__device__ float g_v[S_TOK * DIMC];
__device__ float g_attn[S_TOK * DIMC];
__device__ float g_x[S_TOK * DIMC];          // tf32-rounded x
__device__ float g_wq[DIMC * DIMC];          // tf32-rounded weights
__device__ float g_wk[DIMC * DIMC];
__device__ float g_wv[DIMC * DIMC];
__device__ float g_wo[DIMC * DIMC];

// ---------------------------------------------------------------------------
// tf32 / async helpers
// ---------------------------------------------------------------------------
__device__ __forceinline__ unsigned f2tf(float x) {
    unsigned r;
    asm("cvt.rna.tf32.f32 %0, %1;" : "=r"(r) : "f"(x));
    return r;
}
__device__ __forceinline__ float f2tf_f(float x) {
    return __uint_as_float(f2tf(x));
}
__device__ __forceinline__ void mma_tf32(float* d, const unsigned* a,
                                         unsigned b0, unsigned b1) {
    asm volatile(
        "mma.sync.aligned.m16n8k8.row.col.f32.tf32.tf32.f32 "
        "{%0,%1,%2,%3}, {%4,%5,%6,%7}, {%8,%9}, {%0,%1,%2,%3};\n"
        : "+f"(d[0]), "+f"(d[1]), "+f"(d[2]), "+f"(d[3])
        : "r"(a[0]), "r"(a[1]), "r"(a[2]), "r"(a[3]), "r"(b0), "r"(b1));
}
__device__ __forceinline__ void ldsm_x4(uint4& d, unsigned addr) {
    asm volatile("ldmatrix.sync.aligned.m8n8.x4.shared.b16 {%0,%1,%2,%3}, [%4];"
                 : "=r"(d.x), "=r"(d.y), "=r"(d.z), "=r"(d.w) : "r"(addr));
}
#define CP16(dst, src) \
    asm volatile("cp.async.cg.shared.global [%0], [%1], 16;" :: "r"(dst), "l"(src))
#define CP_COMMIT() asm volatile("cp.async.commit_group;")
#define CP_WAIT(n)  asm volatile("cp.async.wait_group %0;" :: "n"(n))

// ---------------------------------------------------------------------------
// Pre-round fp32 -> tf32 bit pattern (elementwise, float4)
// ---------------------------------------------------------------------------
__global__ void cvt_tf32_kernel(const float* __restrict__ src,
                                float* __restrict__ dst, int n4)
{
    int i = blockIdx.x * blockDim.x + threadIdx.x;
    if (i < n4) {
        float4 v = ((const float4*)src)[i];
        uint4 u;
        u.x = f2tf(v.x); u.y = f2tf(v.y); u.z = f2tf(v.z); u.w = f2tf(v.w);
        ((uint4*)dst)[i] = u;
    }
}

// ---------------------------------------------------------------------------
// tf32 tensor-core GEMM: C = A[4032,1536] @ B[1536,1536] + bias
// A, B hold tf32-rounded bit patterns already. CTA 128x128, K-step 32,
// 3-stage cp.async pipeline, ldmatrix A-frags, zero cvt in hot loop.
// 256 threads = 8 warps (2m x 4n), warp tile 64x32.
// As: [m(128)][k(32)+4pad]  (stride 36 words)
// Bs: [k(32)][n(128)+4pad]  (stride 132 words)
// ---------------------------------------------------------------------------
#define AS_W 36
#define BS_W 132
#define A_WORDS (128 * AS_W)          // 4608
#define B_WORDS (32 * BS_W)           // 4224
#define BUF_WORDS (A_WORDS + B_WORDS) // 8832
#define N_STAGE 3
#define GEMM_SMEM_BYTES (N_STAGE * BUF_WORDS * 4)   // 105,984

__device__ __forceinline__ void gemm_tc(const float* __restrict__ A,
                                        const float* __restrict__ B,
                                        const float* __restrict__ bias,
                                        float* __restrict__ C,
                                        int row0, int col0,
                                        unsigned* smu, bool round_out)
{
    const int tid  = threadIdx.x;
    const int lane = tid & 31;
    const int warp = tid >> 5;
    const int wm = warp >> 2;       // 0..1
    const int wn = warp & 3;        // 0..3
    const int r  = lane >> 2;       // 0..7
    const int c  = lane & 3;        // 0..3

    const int a_lrow  = lane & 15;
    const int a_lhalf = (lane >> 4) << 2;

    const int st_arow = tid >> 3;           // 0..31
    const int st_ak   = (tid & 7) << 2;     // 0..28
    const int st_bk   = tid >> 5;           // 0..7
    const int st_bn   = (tid & 31) << 2;    // 0..124

    float acc[4][4][4];
#pragma unroll
    for (int mt = 0; mt < 4; mt++)
#pragma unroll
        for (int nt = 0; nt < 4; nt++)
#pragma unroll
            for (int i = 0; i < 4; i++) acc[mt][nt][i] = 0.f;

    auto issue_tile = [&](int kb, int buf) {
        unsigned abase = (unsigned)__cvta_generic_to_shared(&smu[buf * BUF_WORDS]);
        unsigned bbase = (unsigned)__cvta_generic_to_shared(&smu[buf * BUF_WORDS + A_WORDS]);
#pragma unroll
        for (int p = 0; p < 4; p++) {
            int row  = st_arow + p * 32;
            int grow = row0 + row;
            grow = (grow < S_TOK) ? grow : (S_TOK - 1);
            CP16(abase + (unsigned)(row * AS_W + st_ak) * 4,
                 &A[(size_t)grow * DIMC + kb + st_ak]);
            int kr = st_bk + p * 8;
            CP16(bbase + (unsigned)(kr * BS_W + st_bn) * 4,
                 &B[(size_t)(kb + kr) * DIMC + col0 + st_bn]);
        }
    };

    auto compute = [&](int buf) {
        const unsigned* As = smu + buf * BUF_WORDS;
        const unsigned* Bs = smu + buf * BUF_WORDS + A_WORDS;
#pragma unroll
        for (int kk = 0; kk < 4; kk++) {
            uint4 a[4];
#pragma unroll
            for (int mt = 0; mt < 4; mt++) {
                unsigned addr = (unsigned)__cvta_generic_to_shared(
                    &As[(wm * 64 + mt * 16 + a_lrow) * AS_W + kk * 8 + a_lhalf]);
                ldsm_x4(a[mt], addr);
            }
            uint2 b[4];
#pragma unroll
            for (int nt = 0; nt < 4; nt++) {
                int nb = wn * 32 + nt * 8 + r;
                b[nt].x = Bs[(kk * 8 + c) * BS_W + nb];
                b[nt].y = Bs[(kk * 8 + c + 4) * BS_W + nb];
            }
#pragma unroll
            for (int mt = 0; mt < 4; mt++)
#pragma unroll
                for (int nt = 0; nt < 4; nt++)
                    mma_tf32(acc[mt][nt], (const unsigned*)&a[mt], b[nt].x, b[nt].y);
        }
    };

    const int NKB = DIMC / 32;   // 48
    issue_tile(0, 0);
    CP_COMMIT();
    issue_tile(32, 1);
    CP_COMMIT();
    for (int kb = 0; kb < NKB; kb++) {
        if (kb < NKB - 1) { CP_WAIT(1); } else { CP_WAIT(0); }
        __syncthreads();
        if (kb + 2 < NKB) {
            issue_tile((kb + 2) * 32, (kb + 2) % N_STAGE);
            CP_COMMIT();
        }
        compute(kb % N_STAGE);
    }

    // Epilogue
#pragma unroll
    for (int mt = 0; mt < 4; mt++) {
        int row_a = row0 + wm * 64 + mt * 16 + r;
        int row_b = row_a + 8;
#pragma unroll
        for (int nt = 0; nt < 4; nt++) {
            int col = col0 + wn * 32 + nt * 8 + 2 * c;
            float b0 = bias[col], b1 = bias[col + 1];
            float v0 = acc[mt][nt][0] + b0, v1 = acc[mt][nt][1] + b1;
            float v2 = acc[mt][nt][2] + b0, v3 = acc[mt][nt][3] + b1;
            if (round_out) {
                v0 = f2tf_f(v0); v1 = f2tf_f(v1);
                v2 = f2tf_f(v2); v3 = f2tf_f(v3);
            }
            if (row_a < S_TOK)
                *(float2*)&C[(size_t)row_a * DIMC + col] = make_float2(v0, v1);
            if (row_b < S_TOK)
                *(float2*)&C[(size_t)row_b * DIMC + col] = make_float2(v2, v3);
        }
    }
}

__global__ void __launch_bounds__(256)
qkv_gemm(const float* __restrict__ bq, const float* __restrict__ bk,
         const float* __restrict__ bv)
{
    extern __shared__ unsigned smu[];
    int z = blockIdx.z;
    const float* B    = (z == 0) ? g_wq : ((z == 1) ? g_wk : g_wv);
    const float* bias = (z == 0) ? bq : ((z == 1) ? bk : bv);
    float* C          = (z == 0) ? g_q : ((z == 1) ? g_k : g_v);
    gemm_tc(g_x, B, bias, C, blockIdx.y * 128, blockIdx.x * 128, smu, z == 2);
}

__global__ void __launch_bounds__(256)
out_gemm(const float* __restrict__ bo, float* __restrict__ out)
{
    extern __shared__ unsigned smu[];
    gemm_tc(g_attn, g_wo, bo, out, blockIdx.y * 128, blockIdx.x * 128, smu, false);
}

// ---------------------------------------------------------------------------
// Fused RMSNorm (full DIM) + 3D RoPE, in-place on g_q / g_k; output
// tf32-rounded. One block per token.
// ---------------------------------------------------------------------------
__global__ void norm_rope_kernel(const float* __restrict__ freqs,
                                 const float* __restrict__ gq,
                                 const float* __restrict__ gk)
{
    int s = blockIdx.x;
    int tid = threadIdx.x;
    float* qrow = g_q + (size_t)s * DIMC;
    float* krow = g_k + (size_t)s * DIMC;

    float2 qv[3], kv[3];
    float sq = 0.f, sk = 0.f;
#pragma unroll
    for (int p = 0; p < 3; p++) {
        int pr = tid + p * 256;
        qv[p] = *(const float2*)&qrow[2 * pr];
        kv[p] = *(const float2*)&krow[2 * pr];
        sq += qv[p].x * qv[p].x + qv[p].y * qv[p].y;
        sk += kv[p].x * kv[p].x + kv[p].y * kv[p].y;
    }
    __shared__ float red[2][8];
#pragma unroll
    for (int o = 16; o > 0; o >>= 1) {
        sq += __shfl_down_sync(0xffffffffu, sq, o);
        sk += __shfl_down_sync(0xffffffffu, sk, o);
    }
    int warp = tid >> 5;
    if ((tid & 31) == 0) { red[0][warp] = sq; red[1][warp] = sk; }
    __syncthreads();
    sq = 0.f; sk = 0.f;
#pragma unroll
    for (int w = 0; w < 8; w++) { sq += red[0][w]; sk += red[1][w]; }
    float rq = rsqrtf(sq * (1.f / DIMC) + 1e-6f);
    float rk = rsqrtf(sk * (1.f / DIMC) + 1e-6f);

    int f = s / FRAME;
    int rem = s % FRAME;
    int hh = rem / 28;
    int ww = rem % 28;
#pragma unroll
    for (int p = 0; p < 3; p++) {
        int pr = tid + p * 256;
        int rot = pr & 63;
        float a;
        if (rot < 22)       a = freqs[f  * ROTC + rot];
        else if (rot < 43)  a = freqs[hh * ROTC + rot];
        else                a = freqs[ww * ROTC + rot];
        float cc = cosf(a), sn = sinf(a);
        float q0 = qv[p].x * rq * gq[2 * pr];
        float q1 = qv[p].y * rq * gq[2 * pr + 1];
        float k0 = kv[p].x * rk * gk[2 * pr];
        float k1 = kv[p].y * rk * gk[2 * pr + 1];
        *(float2*)&qrow[2 * pr] =
            make_float2(f2tf_f(q0 * cc - q1 * sn), f2tf_f(q0 * sn + q1 * cc));
        *(float2*)&krow[2 * pr] =
            make_float2(f2tf_f(k0 * cc - k1 * sn), f2tf_f(k0 * sn + k1 * cc));
    }
}

// ---------------------------------------------------------------------------
// Frame-causal flash attention, tf32 tensor cores.
// Q/K/V are tf32-rounded in gmem: staging = pure uint4 copies, no cvt.
// Scale folded into exp arguments. Block = (64 q-rows, head), 128 threads.
// ---------------------------------------------------------------------------
#define QS_OFF 0
#define KS_OFF (64 * 132)
#define VS_OFF (128 * 132)
#define ATTN_SMEM_U (192 * 132)
#define PS_STRIDE 68

__global__ void __launch_bounds__(128)
attn_kernel()
{
    extern __shared__ unsigned asm_u[];
    unsigned* Qs = asm_u + QS_OFF;
    unsigned* Ps = asm_u + QS_OFF;    // alias (Qs dead after frag load)
    unsigned* Ks = asm_u + KS_OFF;
    unsigned* Vs = asm_u + VS_OFF;

    const int tid  = threadIdx.x;
    const int lane = tid & 31;
    const int w    = tid >> 5;
    const int r    = lane >> 2;
    const int c    = lane & 3;
    const int w16  = w * 16;

    const int row0 = blockIdx.x * 64;
    const int h    = blockIdx.y;
    const int ktiles = (row0 / FRAME + 1) * (FRAME / 64);
    const float scale = 0.08838834764831845f;   // 1/sqrt(128)

    // Stage Q: raw copy (already tf32 bits)
#pragma unroll
    for (int it = 0; it < 16; it++) {
        int idx = tid + it * 128;
        int rr = idx >> 5;
        int cc = (idx & 31) << 2;
        *(uint4*)&Qs[rr * 132 + cc] =
            *(const uint4*)&g_q[(size_t)(row0 + rr) * DIMC + h * HDIM + cc];
    }
    __syncthreads();

    unsigned qa[16][4];
#pragma unroll
    for (int dt = 0; dt < 16; dt++) {
        qa[dt][0] = Qs[(w16 + r) * 132 + dt * 8 + c];
        qa[dt][1] = Qs[(w16 + r + 8) * 132 + dt * 8 + c];
        qa[dt][2] = Qs[(w16 + r) * 132 + dt * 8 + c + 4];
        qa[dt][3] = Qs[(w16 + r + 8) * 132 + dt * 8 + c + 4];
    }

    float O[16][4];
#pragma unroll
    for (int nt = 0; nt < 16; nt++)
#pragma unroll
        for (int i = 0; i < 4; i++) O[nt][i] = 0.f;
    float m0 = -1e30f, m1 = -1e30f, l0 = 0.f, l1 = 0.f;

    for (int kt = 0; kt < ktiles; kt++) {
        int krow0 = kt * 64;
        __syncthreads();
        // Stage K, V: raw copies
#pragma unroll
        for (int it = 0; it < 16; it++) {
            int idx = tid + it * 128;
            int rr = idx >> 5;
            int cc = (idx & 31) << 2;
            *(uint4*)&Ks[rr * 132 + cc] =
                *(const uint4*)&g_k[(size_t)(krow0 + rr) * DIMC + h * HDIM + cc];
            *(uint4*)&Vs[rr * 132 + cc] =
                *(const uint4*)&g_v[(size_t)(krow0 + rr) * DIMC + h * HDIM + cc];
        }
        __syncthreads();

        float S[8][4];
#pragma unroll
        for (int nt = 0; nt < 8; nt++)
#pragma unroll
            for (int i = 0; i < 4; i++) S[nt][i] = 0.f;
#pragma unroll
        for (int dt = 0; dt < 16; dt++) {
#pragma unroll
            for (int nt = 0; nt < 8; nt++) {
                unsigned b0 = Ks[(nt * 8 + r) * 132 + dt * 8 + c];
                unsigned b1 = Ks[(nt * 8 + r) * 132 + dt * 8 + c + 4];
                mma_tf32(S[nt], qa[dt], b0, b1);
            }
        }

        float mx0 = -1e30f, mx1 = -1e30f;
#pragma unroll
        for (int nt = 0; nt < 8; nt++) {
            mx0 = fmaxf(mx0, fmaxf(S[nt][0], S[nt][1]));
            mx1 = fmaxf(mx1, fmaxf(S[nt][2], S[nt][3]));
        }
        mx0 = fmaxf(mx0, __shfl_xor_sync(0xffffffffu, mx0, 1));
        mx0 = fmaxf(mx0, __shfl_xor_sync(0xffffffffu, mx0, 2));
        mx1 = fmaxf(mx1, __shfl_xor_sync(0xffffffffu, mx1, 1));
        mx1 = fmaxf(mx1, __shfl_xor_sync(0xffffffffu, mx1, 2));
        float mn0 = fmaxf(m0, mx0), mn1 = fmaxf(m1, mx1);
        float fac0 = __expf((m0 - mn0) * scale);
        float fac1 = __expf((m1 - mn1) * scale);

        __syncwarp();
        float sum0 = 0.f, sum1 = 0.f;
#pragma unroll
        for (int nt = 0; nt < 8; nt++) {
            float p00 = __expf((S[nt][0] - mn0) * scale);
            float p01 = __expf((S[nt][1] - mn0) * scale);
            float p10 = __expf((S[nt][2] - mn1) * scale);
            float p11 = __expf((S[nt][3] - mn1) * scale);
            sum0 += p00 + p01;
            sum1 += p10 + p11;
            *(uint2*)&Ps[(w16 + r) * PS_STRIDE + nt * 8 + 2 * c] =
                make_uint2(f2tf(p00), f2tf(p01));
            *(uint2*)&Ps[(w16 + r + 8) * PS_STRIDE + nt * 8 + 2 * c] =
                make_uint2(f2tf(p10), f2tf(p11));
        }
        sum0 += __shfl_xor_sync(0xffffffffu, sum0, 1);
        sum0 += __shfl_xor_sync(0xffffffffu, sum0, 2);
        sum1 += __shfl_xor_sync(0xffffffffu, sum1, 1);
        sum1 += __shfl_xor_sync(0xffffffffu, sum1, 2);
        l0 = l0 * fac0 + sum0;
        l1 = l1 * fac1 + sum1;
        m0 = mn0; m1 = mn1;

#pragma unroll
        for (int nt = 0; nt < 16; nt++) {
            O[nt][0] *= fac0; O[nt][1] *= fac0;
            O[nt][2] *= fac1; O[nt][3] *= fac1;
        }
        __syncwarp();

#pragma unroll
        for (int k8 = 0; k8 < 8; k8++) {
            unsigned pa[4];
            pa[0] = Ps[(w16 + r) * PS_STRIDE + k8 * 8 + c];
            pa[1] = Ps[(w16 + r + 8) * PS_STRIDE + k8 * 8 + c];
            pa[2] = Ps[(w16 + r) * PS_STRIDE + k8 * 8 + c + 4];
            pa[3] = Ps[(w16 + r + 8) * PS_STRIDE + k8 * 8 + c + 4];
#pragma unroll
            for (int nt = 0; nt < 16; nt++) {
                unsigned b0 = Vs[(k8 * 8 + c) * 132 + nt * 8 + r];
                unsigned b1 = Vs[(k8 * 8 + c + 4) * 132 + nt * 8 + r];
                mma_tf32(O[nt], pa, b0, b1);
            }
        }
    }

    // Epilogue: normalize, tf32-round (out_gemm consumes raw bits)
    float inv0 = 1.f / l0, inv1 = 1.f / l1;
    int row_a = row0 + w16 + r;
    int row_b = row_a + 8;
#pragma unroll
    for (int nt = 0; nt < 16; nt++) {
        int col = h * HDIM + nt * 8 + 2 * c;
        *(float2*)&g_attn[(size_t)row_a * DIMC + col] =
            make_float2(f2tf_f(O[nt][0] * inv0), f2tf_f(O[nt][1] * inv0));
        *(float2*)&g_attn[(size_t)row_b * DIMC + col] =
            make_float2(f2tf_f(O[nt][2] * inv1), f2tf_f(O[nt][3] * inv1));
    }
}

// ---------------------------------------------------------------------------
extern "C" void kernel_launch(void* const* d_in, const int* in_sizes, int n_in,
                              void* d_out, int out_size)
{
    (void)in_sizes; (void)n_in; (void)out_size;
    const float* x     = (const float*)d_in[0];
    const float* freqs = (const float*)d_in[3];
    const float* Wq    = (const float*)d_in[4];
    const float* bq    = (const float*)d_in[5];
    const float* Wk    = (const float*)d_in[6];
    const float* bk    = (const float*)d_in[7];
    const float* Wv    = (const float*)d_in[8];
    const float* bv    = (const float*)d_in[9];
    const float* Wo    = (const float*)d_in[10];
    const float* bo    = (const float*)d_in[11];
    const float* gq    = (const float*)d_in[12];
    const float* gk    = (const float*)d_in[13];
    float* out = (float*)d_out;

    const int gemm_smem = GEMM_SMEM_BYTES;   // 105,984 B
    const int attn_smem = ATTN_SMEM_U * 4;   // 101,376 B
    cudaFuncSetAttribute(qkv_gemm,
                         cudaFuncAttributeMaxDynamicSharedMemorySize, gemm_smem);
    cudaFuncSetAttribute(out_gemm,
                         cudaFuncAttributeMaxDynamicSharedMemorySize, gemm_smem);
    cudaFuncSetAttribute(attn_kernel,
                         cudaFuncAttributeMaxDynamicSharedMemorySize, attn_smem);

    // Pre-round x and weights to tf32 bit patterns
    float* dxp; float* dwq; float* dwk; float* dwv; float* dwo;
    cudaGetSymbolAddress((void**)&dxp, g_x);
    cudaGetSymbolAddress((void**)&dwq, g_wq);
    cudaGetSymbolAddress((void**)&dwk, g_wk);
    cudaGetSymbolAddress((void**)&dwv, g_wv);
    cudaGetSymbolAddress((void**)&dwo, g_wo);
    const int NX4 = S_TOK * DIMC / 4;      // 1,548,288
    const int NW4 = DIMC * DIMC / 4;       // 589,824
    cvt_tf32_kernel<<<(NX4 + 255) / 256, 256>>>(x,  dxp, NX4);
    cvt_tf32_kernel<<<(NW4 + 255) / 256, 256>>>(Wq, dwq, NW4);
    cvt_tf32_kernel<<<(NW4 + 255) / 256, 256>>>(Wk, dwk, NW4);
    cvt_tf32_kernel<<<(NW4 + 255) / 256, 256>>>(Wv, dwv, NW4);
    cvt_tf32_kernel<<<(NW4 + 255) / 256, 256>>>(Wo, dwo, NW4);

    qkv_gemm<<<dim3(12, 32, 3), 256, gemm_smem>>>(bq, bk, bv);
    norm_rope_kernel<<<S_TOK, 256>>>(freqs, gq, gk);
    attn_kernel<<<dim3(63, 12), 128, attn_smem>>>();
    out_gemm<<<dim3(12, 32), 256, gemm_smem>>>(bo, out);
}

// round 6
// speedup vs baseline: 3.0581x; 1.1623x over previous
#include <cuda_runtime.h>
#include <math.h>

#define S_TOK 4032
#define DIMC  1536
#define NHEAD 12
#define HDIM  128
#define ROTC  64
#define FRAME 448

// Scratch (device globals: no allocation allowed in kernel_launch)
__device__ float g_q[S_TOK * DIMC];
__device__ float g_k[S_TOK * DIMC];
__device__ float g_v[S_TOK * DIMC];
__device__ float g_attn[S_TOK * DIMC];
__device__ float g_x[S_TOK * DIMC];          // tf32-rounded x
__device__ float g_wq[DIMC * DIMC];          // tf32-rounded weights
__device__ float g_wk[DIMC * DIMC];
__device__ float g_wv[DIMC * DIMC];
__device__ float g_wo[DIMC * DIMC];

// ---------------------------------------------------------------------------
// tf32 / async helpers
// ---------------------------------------------------------------------------
__device__ __forceinline__ unsigned f2tf(float x) {
    unsigned r;
    asm("cvt.rna.tf32.f32 %0, %1;" : "=r"(r) : "f"(x));
    return r;
}
__device__ __forceinline__ float f2tf_f(float x) {
    return __uint_as_float(f2tf(x));
}
__device__ __forceinline__ void mma_tf32(float* d, const unsigned* a,
                                         unsigned b0, unsigned b1) {
    asm volatile(
        "mma.sync.aligned.m16n8k8.row.col.f32.tf32.tf32.f32 "
        "{%0,%1,%2,%3}, {%4,%5,%6,%7}, {%8,%9}, {%0,%1,%2,%3};\n"
        : "+f"(d[0]), "+f"(d[1]), "+f"(d[2]), "+f"(d[3])
        : "r"(a[0]), "r"(a[1]), "r"(a[2]), "r"(a[3]), "r"(b0), "r"(b1));
}
__device__ __forceinline__ void ldsm_x4(uint4& d, unsigned addr) {
    asm volatile("ldmatrix.sync.aligned.m8n8.x4.shared.b16 {%0,%1,%2,%3}, [%4];"
                 : "=r"(d.x), "=r"(d.y), "=r"(d.z), "=r"(d.w) : "r"(addr));
}
#define CP16(dst, src) \
    asm volatile("cp.async.cg.shared.global [%0], [%1], 16;" :: "r"(dst), "l"(src))
#define CP_COMMIT() asm volatile("cp.async.commit_group;")
#define CP_WAIT(n)  asm volatile("cp.async.wait_group %0;" :: "n"(n))

// ---------------------------------------------------------------------------
// Pre-round fp32 -> tf32 bit pattern (elementwise, float4)
// ---------------------------------------------------------------------------
__global__ void cvt_tf32_kernel(const float* __restrict__ src,
                                float* __restrict__ dst, int n4)
{
    int i = blockIdx.x * blockDim.x + threadIdx.x;
    if (i < n4) {
        float4 v = ((const float4*)src)[i];
        uint4 u;
        u.x = f2tf(v.x); u.y = f2tf(v.y); u.z = f2tf(v.z); u.w = f2tf(v.w);
        ((uint4*)dst)[i] = u;
    }
}

// ---------------------------------------------------------------------------
// tf32 tensor-core GEMM: C = A[4032,1536] @ B[1536,1536] + bias
// A, B hold tf32-rounded bit patterns. CTA 128x128, K-step 32,
// 3-stage cp.async pipeline, ldmatrix A-frags, conflict-free B loads.
// 256 threads = 8 warps (2m x 4n), warp tile 64x32.
// As: [m(128)][k(32)+4pad]   stride 36  (ldmatrix rows land 4 banks apart)
// Bs: [k(32)][n(128)+8pad]   stride 136 (8c+r all-distinct banks)
// ---------------------------------------------------------------------------
#define AS_W 36
#define BS_W 136
#define A_WORDS (128 * AS_W)          // 4608
#define B_WORDS (32 * BS_W)           // 4352
#define BUF_WORDS (A_WORDS + B_WORDS) // 8960
#define N_STAGE 3
#define GEMM_SMEM_BYTES (N_STAGE * BUF_WORDS * 4)   // 107,520

__device__ __forceinline__ void gemm_tc(const float* __restrict__ A,
                                        const float* __restrict__ B,
                                        const float* __restrict__ bias,
                                        float* __restrict__ C,
                                        int row0, int col0,
                                        unsigned* smu, bool round_out)
{
    const int tid  = threadIdx.x;
    const int lane = tid & 31;
    const int warp = tid >> 5;
    const int wm = warp >> 2;       // 0..1
    const int wn = warp & 3;        // 0..3
    const int r  = lane >> 2;       // 0..7
    const int c  = lane & 3;        // 0..3

    const int a_lrow  = lane & 15;
    const int a_lhalf = (lane >> 4) << 2;

    const int st_arow = tid >> 3;           // 0..31
    const int st_ak   = (tid & 7) << 2;     // 0..28
    const int st_bk   = tid >> 5;           // 0..7
    const int st_bn   = (tid & 31) << 2;    // 0..124

    float acc[4][4][4];
#pragma unroll
    for (int mt = 0; mt < 4; mt++)
#pragma unroll
        for (int nt = 0; nt < 4; nt++)
#pragma unroll
            for (int i = 0; i < 4; i++) acc[mt][nt][i] = 0.f;

    auto issue_tile = [&](int kb, int buf) {
        unsigned abase = (unsigned)__cvta_generic_to_shared(&smu[buf * BUF_WORDS]);
        unsigned bbase = (unsigned)__cvta_generic_to_shared(&smu[buf * BUF_WORDS + A_WORDS]);
#pragma unroll
        for (int p = 0; p < 4; p++) {
            int row  = st_arow + p * 32;
            int grow = row0 + row;
            grow = (grow < S_TOK) ? grow : (S_TOK - 1);
            CP16(abase + (unsigned)(row * AS_W + st_ak) * 4,
                 &A[(size_t)grow * DIMC + kb + st_ak]);
            int kr = st_bk + p * 8;
            CP16(bbase + (unsigned)(kr * BS_W + st_bn) * 4,
                 &B[(size_t)(kb + kr) * DIMC + col0 + st_bn]);
        }
    };

    auto compute = [&](int buf) {
        const unsigned* As = smu + buf * BUF_WORDS;
        const unsigned* Bs = smu + buf * BUF_WORDS + A_WORDS;
#pragma unroll
        for (int kk = 0; kk < 4; kk++) {
            uint4 a[4];
#pragma unroll
            for (int mt = 0; mt < 4; mt++) {
                unsigned addr = (unsigned)__cvta_generic_to_shared(
                    &As[(wm * 64 + mt * 16 + a_lrow) * AS_W + kk * 8 + a_lhalf]);
                ldsm_x4(a[mt], addr);
            }
            uint2 b[4];
#pragma unroll
            for (int nt = 0; nt < 4; nt++) {
                int nb = wn * 32 + nt * 8 + r;
                b[nt].x = Bs[(kk * 8 + c) * BS_W + nb];
                b[nt].y = Bs[(kk * 8 + c + 4) * BS_W + nb];
            }
#pragma unroll
            for (int mt = 0; mt < 4; mt++)
#pragma unroll
                for (int nt = 0; nt < 4; nt++)
                    mma_tf32(acc[mt][nt], (const unsigned*)&a[mt], b[nt].x, b[nt].y);
        }
    };

    const int NKB = DIMC / 32;   // 48
    issue_tile(0, 0);
    CP_COMMIT();
    issue_tile(32, 1);
    CP_COMMIT();
    for (int kb = 0; kb < NKB; kb++) {
        if (kb < NKB - 1) { CP_WAIT(1); } else { CP_WAIT(0); }
        __syncthreads();
        if (kb + 2 < NKB) {
            issue_tile((kb + 2) * 32, (kb + 2) % N_STAGE);
            CP_COMMIT();
        }
        compute(kb % N_STAGE);
    }

    // Epilogue
#pragma unroll
    for (int mt = 0; mt < 4; mt++) {
        int row_a = row0 + wm * 64 + mt * 16 + r;
        int row_b = row_a + 8;
#pragma unroll
        for (int nt = 0; nt < 4; nt++) {
            int col = col0 + wn * 32 + nt * 8 + 2 * c;
            float b0 = bias[col], b1 = bias[col + 1];
            float v0 = acc[mt][nt][0] + b0, v1 = acc[mt][nt][1] + b1;
            float v2 = acc[mt][nt][2] + b0, v3 = acc[mt][nt][3] + b1;
            if (round_out) {
                v0 = f2tf_f(v0); v1 = f2tf_f(v1);
                v2 = f2tf_f(v2); v3 = f2tf_f(v3);
            }
            if (row_a < S_TOK)
                *(float2*)&C[(size_t)row_a * DIMC + col] = make_float2(v0, v1);
            if (row_b < S_TOK)
                *(float2*)&C[(size_t)row_b * DIMC + col] = make_float2(v2, v3);
        }
    }
}

__global__ void __launch_bounds__(256)
qkv_gemm(const float* __restrict__ bq, const float* __restrict__ bk,
         const float* __restrict__ bv)
{
    extern __shared__ unsigned smu[];
    int z = blockIdx.z;
    const float* B    = (z == 0) ? g_wq : ((z == 1) ? g_wk : g_wv);
    const float* bias = (z == 0) ? bq : ((z == 1) ? bk : bv);
    float* C          = (z == 0) ? g_q : ((z == 1) ? g_k : g_v);
    gemm_tc(g_x, B, bias, C, blockIdx.y * 128, blockIdx.x * 128, smu, z == 2);
}

__global__ void __launch_bounds__(256)
out_gemm(const float* __restrict__ bo, float* __restrict__ out)
{
    extern __shared__ unsigned smu[];
    gemm_tc(g_attn, g_wo, bo, out, blockIdx.y * 128, blockIdx.x * 128, smu, false);
}

// ---------------------------------------------------------------------------
// Fused RMSNorm (full DIM) + 3D RoPE, in-place on g_q / g_k; output
// tf32-rounded. One block per token.
// ---------------------------------------------------------------------------
__global__ void norm_rope_kernel(const float* __restrict__ freqs,
                                 const float* __restrict__ gq,
                                 const float* __restrict__ gk)
{
    int s = blockIdx.x;
    int tid = threadIdx.x;
    float* qrow = g_q + (size_t)s * DIMC;
    float* krow = g_k + (size_t)s * DIMC;

    float2 qv[3], kv[3];
    float sq = 0.f, sk = 0.f;
#pragma unroll
    for (int p = 0; p < 3; p++) {
        int pr = tid + p * 256;
        qv[p] = *(const float2*)&qrow[2 * pr];
        kv[p] = *(const float2*)&krow[2 * pr];
        sq += qv[p].x * qv[p].x + qv[p].y * qv[p].y;
        sk += kv[p].x * kv[p].x + kv[p].y * kv[p].y;
    }
    __shared__ float red[2][8];
#pragma unroll
    for (int o = 16; o > 0; o >>= 1) {
        sq += __shfl_down_sync(0xffffffffu, sq, o);
        sk += __shfl_down_sync(0xffffffffu, sk, o);
    }
    int warp = tid >> 5;
    if ((tid & 31) == 0) { red[0][warp] = sq; red[1][warp] = sk; }
    __syncthreads();
    sq = 0.f; sk = 0.f;
#pragma unroll
    for (int w = 0; w < 8; w++) { sq += red[0][w]; sk += red[1][w]; }
    float rq = rsqrtf(sq * (1.f / DIMC) + 1e-6f);
    float rk = rsqrtf(sk * (1.f / DIMC) + 1e-6f);

    int f = s / FRAME;
    int rem = s % FRAME;
    int hh = rem / 28;
    int ww = rem % 28;
#pragma unroll
    for (int p = 0; p < 3; p++) {
        int pr = tid + p * 256;
        int rot = pr & 63;
        float a;
        if (rot < 22)       a = freqs[f  * ROTC + rot];
        else if (rot < 43)  a = freqs[hh * ROTC + rot];
        else                a = freqs[ww * ROTC + rot];
        float cc = cosf(a), sn = sinf(a);
        float q0 = qv[p].x * rq * gq[2 * pr];
        float q1 = qv[p].y * rq * gq[2 * pr + 1];
        float k0 = kv[p].x * rk * gk[2 * pr];
        float k1 = kv[p].y * rk * gk[2 * pr + 1];
        *(float2*)&qrow[2 * pr] =
            make_float2(f2tf_f(q0 * cc - q1 * sn), f2tf_f(q0 * sn + q1 * cc));
        *(float2*)&krow[2 * pr] =
            make_float2(f2tf_f(k0 * cc - k1 * sn), f2tf_f(k0 * sn + k1 * cc));
    }
}

// ---------------------------------------------------------------------------
// Frame-causal flash attention, tf32 tensor cores.
// Q/K/V tf32-rounded in gmem: staging = pure uint4 copies.
// Block = (64 q-rows, head), 128 threads. Longest q-tiles launch first.
// Ks stride 132 (reads 4r+c: conflict-free); Vs stride 136 (reads 8c+r: cf).
// ---------------------------------------------------------------------------
#define QS_W 132
#define KS_W 132
#define VS_W 136
#define QS_OFF 0
#define KS_OFF (64 * QS_W)
#define VS_OFF (KS_OFF + 64 * KS_W)
#define ATTN_SMEM_U (VS_OFF + 64 * VS_W)   // 25,600 words = 102,400 B
#define PS_STRIDE 68

__global__ void __launch_bounds__(128)
attn_kernel()
{
    extern __shared__ unsigned asm_u[];
    unsigned* Qs = asm_u + QS_OFF;
    unsigned* Ps = asm_u + QS_OFF;    // alias (Qs dead after frag load)
    unsigned* Ks = asm_u + KS_OFF;
    unsigned* Vs = asm_u + VS_OFF;

    const int tid  = threadIdx.x;
    const int lane = tid & 31;
    const int w    = tid >> 5;
    const int r    = lane >> 2;
    const int c    = lane & 3;
    const int w16  = w * 16;

    const int qb   = 62 - blockIdx.x;          // longest blocks first
    const int row0 = qb * 64;
    const int h    = blockIdx.y;
    const int ktiles = (row0 / FRAME + 1) * (FRAME / 64);
    const float scale = 0.08838834764831845f;   // 1/sqrt(128)

    // Stage Q: raw copy (already tf32 bits)
#pragma unroll
    for (int it = 0; it < 16; it++) {
        int idx = tid + it * 128;
        int rr = idx >> 5;
        int cc = (idx & 31) << 2;
        *(uint4*)&Qs[rr * QS_W + cc] =
            *(const uint4*)&g_q[(size_t)(row0 + rr) * DIMC + h * HDIM + cc];
    }
    __syncthreads();

    unsigned qa[16][4];
#pragma unroll
    for (int dt = 0; dt < 16; dt++) {
        qa[dt][0] = Qs[(w16 + r) * QS_W + dt * 8 + c];
        qa[dt][1] = Qs[(w16 + r + 8) * QS_W + dt * 8 + c];
        qa[dt][2] = Qs[(w16 + r) * QS_W + dt * 8 + c + 4];
        qa[dt][3] = Qs[(w16 + r + 8) * QS_W + dt * 8 + c + 4];
    }

    float O[16][4];
#pragma unroll
    for (int nt = 0; nt < 16; nt++)
#pragma unroll
        for (int i = 0; i < 4; i++) O[nt][i] = 0.f;
    float m0 = -1e30f, m1 = -1e30f, l0 = 0.f, l1 = 0.f;

    for (int kt = 0; kt < ktiles; kt++) {
        int krow0 = kt * 64;
        __syncthreads();
        // Stage K, V: raw copies
#pragma unroll
        for (int it = 0; it < 16; it++) {
            int idx = tid + it * 128;
            int rr = idx >> 5;
            int cc = (idx & 31) << 2;
            *(uint4*)&Ks[rr * KS_W + cc] =
                *(const uint4*)&g_k[(size_t)(krow0 + rr) * DIMC + h * HDIM + cc];
            *(uint4*)&Vs[rr * VS_W + cc] =
                *(const uint4*)&g_v[(size_t)(krow0 + rr) * DIMC + h * HDIM + cc];
        }
        __syncthreads();

        float S[8][4];
#pragma unroll
        for (int nt = 0; nt < 8; nt++)
#pragma unroll
            for (int i = 0; i < 4; i++) S[nt][i] = 0.f;
#pragma unroll
        for (int dt = 0; dt < 16; dt++) {
#pragma unroll
            for (int nt = 0; nt < 8; nt++) {
                unsigned b0 = Ks[(nt * 8 + r) * KS_W + dt * 8 + c];
                unsigned b1 = Ks[(nt * 8 + r) * KS_W + dt * 8 + c + 4];
                mma_tf32(S[nt], qa[dt], b0, b1);
            }
        }

        float mx0 = -1e30f, mx1 = -1e30f;
#pragma unroll
        for (int nt = 0; nt < 8; nt++) {
            mx0 = fmaxf(mx0, fmaxf(S[nt][0], S[nt][1]));
            mx1 = fmaxf(mx1, fmaxf(S[nt][2], S[nt][3]));
        }
        mx0 = fmaxf(mx0, __shfl_xor_sync(0xffffffffu, mx0, 1));
        mx0 = fmaxf(mx0, __shfl_xor_sync(0xffffffffu, mx0, 2));
        mx1 = fmaxf(mx1, __shfl_xor_sync(0xffffffffu, mx1, 1));
        mx1 = fmaxf(mx1, __shfl_xor_sync(0xffffffffu, mx1, 2));
        float mn0 = fmaxf(m0, mx0), mn1 = fmaxf(m1, mx1);
        float fac0 = __expf((m0 - mn0) * scale);
        float fac1 = __expf((m1 - mn1) * scale);

        __syncwarp();
        float sum0 = 0.f, sum1 = 0.f;
#pragma unroll
        for (int nt = 0; nt < 8; nt++) {
            float p00 = __expf((S[nt][0] - mn0) * scale);
            float p01 = __expf((S[nt][1] - mn0) * scale);
            float p10 = __expf((S[nt][2] - mn1) * scale);
            float p11 = __expf((S[nt][3] - mn1) * scale);
            sum0 += p00 + p01;
            sum1 += p10 + p11;
            *(uint2*)&Ps[(w16 + r) * PS_STRIDE + nt * 8 + 2 * c] =
                make_uint2(f2tf(p00), f2tf(p01));
            *(uint2*)&Ps[(w16 + r + 8) * PS_STRIDE + nt * 8 + 2 * c] =
                make_uint2(f2tf(p10), f2tf(p11));
        }
        sum0 += __shfl_xor_sync(0xffffffffu, sum0, 1);
        sum0 += __shfl_xor_sync(0xffffffffu, sum0, 2);
        sum1 += __shfl_xor_sync(0xffffffffu, sum1, 1);
        sum1 += __shfl_xor_sync(0xffffffffu, sum1, 2);
        l0 = l0 * fac0 + sum0;
        l1 = l1 * fac1 + sum1;
        m0 = mn0; m1 = mn1;

#pragma unroll
        for (int nt = 0; nt < 16; nt++) {
            O[nt][0] *= fac0; O[nt][1] *= fac0;
            O[nt][2] *= fac1; O[nt][3] *= fac1;
        }
        __syncwarp();

#pragma unroll
        for (int k8 = 0; k8 < 8; k8++) {
            unsigned pa[4];
            pa[0] = Ps[(w16 + r) * PS_STRIDE + k8 * 8 + c];
            pa[1] = Ps[(w16 + r + 8) * PS_STRIDE + k8 * 8 + c];
            pa[2] = Ps[(w16 + r) * PS_STRIDE + k8 * 8 + c + 4];
            pa[3] = Ps[(w16 + r + 8) * PS_STRIDE + k8 * 8 + c + 4];
#pragma unroll
            for (int nt = 0; nt < 16; nt++) {
                unsigned b0 = Vs[(k8 * 8 + c) * VS_W + nt * 8 + r];
                unsigned b1 = Vs[(k8 * 8 + c + 4) * VS_W + nt * 8 + r];
                mma_tf32(O[nt], pa, b0, b1);
            }
        }
    }

    // Epilogue: normalize, tf32-round (out_gemm consumes raw bits)
    float inv0 = 1.f / l0, inv1 = 1.f / l1;
    int row_a = row0 + w16 + r;
    int row_b = row_a + 8;
#pragma unroll
    for (int nt = 0; nt < 16; nt++) {
        int col = h * HDIM + nt * 8 + 2 * c;
        *(float2*)&g_attn[(size_t)row_a * DIMC + col] =
            make_float2(f2tf_f(O[nt][0] * inv0), f2tf_f(O[nt][1] * inv0));
        *(float2*)&g_attn[(size_t)row_b * DIMC + col] =
            make_float2(f2tf_f(O[nt][2] * inv1), f2tf_f(O[nt][3] * inv1));
    }
}

// ---------------------------------------------------------------------------
extern "C" void kernel_launch(void* const* d_in, const int* in_sizes, int n_in,
                              void* d_out, int out_size)
{
    (void)in_sizes; (void)n_in; (void)out_size;
    const float* x     = (const float*)d_in[0];
    const float* freqs = (const float*)d_in[3];
    const float* Wq    = (const float*)d_in[4];
    const float* bq    = (const float*)d_in[5];
    const float* Wk    = (const float*)d_in[6];
    const float* bk    = (const float*)d_in[7];
    const float* Wv    = (const float*)d_in[8];
    const float* bv    = (const float*)d_in[9];
    const float* Wo    = (const float*)d_in[10];
    const float* bo    = (const float*)d_in[11];
    const float* gq    = (const float*)d_in[12];
    const float* gk    = (const float*)d_in[13];
    float* out = (float*)d_out;

    const int gemm_smem = GEMM_SMEM_BYTES;   // 107,520 B
    const int attn_smem = ATTN_SMEM_U * 4;   // 102,400 B
    cudaFuncSetAttribute(qkv_gemm,
                         cudaFuncAttributeMaxDynamicSharedMemorySize, gemm_smem);
    cudaFuncSetAttribute(out_gemm,
                         cudaFuncAttributeMaxDynamicSharedMemorySize, gemm_smem);
    cudaFuncSetAttribute(attn_kernel,
                         cudaFuncAttributeMaxDynamicSharedMemorySize, attn_smem);

    // Pre-round x and weights to tf32 bit patterns
    float* dxp; float* dwq; float* dwk; float* dwv; float* dwo;
    cudaGetSymbolAddress((void**)&dxp, g_x);
    cudaGetSymbolAddress((void**)&dwq, g_wq);
    cudaGetSymbolAddress((void**)&dwk, g_wk);
    cudaGetSymbolAddress((void**)&dwv, g_wv);
    cudaGetSymbolAddress((void**)&dwo, g_wo);
    const int NX4 = S_TOK * DIMC / 4;
    const int NW4 = DIMC * DIMC / 4;
    cvt_tf32_kernel<<<(NX4 + 255) / 256, 256>>>(x,  dxp, NX4);
    cvt_tf32_kernel<<<(NW4 + 255) / 256, 256>>>(Wq, dwq, NW4);
    cvt_tf32_kernel<<<(NW4 + 255) / 256, 256>>>(Wk, dwk, NW4);
    cvt_tf32_kernel<<<(NW4 + 255) / 256, 256>>>(Wv, dwv, NW4);
    cvt_tf32_kernel<<<(NW4 + 255) / 256, 256>>>(Wo, dwo, NW4);

    qkv_gemm<<<dim3(12, 32, 3), 256, gemm_smem>>>(bq, bk, bv);
    norm_rope_kernel<<<S_TOK, 256>>>(freqs, gq, gk);
    attn_kernel<<<dim3(63, 12), 128, attn_smem>>>();
    out_gemm<<<dim3(12, 32), 256, gemm_smem>>>(bo, out);
}

// round 7
// speedup vs baseline: 3.1819x; 1.0405x over previous
#include <cuda_runtime.h>
#include <math.h>

#define S_TOK 4032
#define DIMC  1536
#define NHEAD 12
#define HDIM  128
#define ROTC  64
#define FRAME 448

// Scratch (device globals: no allocation allowed in kernel_launch)
__device__ float g_q[S_TOK * DIMC];
__device__ float g_k[S_TOK * DIMC];
__device__ float g_v[S_TOK * DIMC];
__device__ float g_attn[S_TOK * DIMC];
__device__ float g_x[S_TOK * DIMC];          // tf32-rounded x
__device__ float g_wq[DIMC * DIMC];          // tf32-rounded weights
__device__ float g_wk[DIMC * DIMC];
__device__ float g_wv[DIMC * DIMC];
__device__ float g_wo[DIMC * DIMC];

// ---------------------------------------------------------------------------
// tf32 / async helpers
// ---------------------------------------------------------------------------
__device__ __forceinline__ unsigned f2tf(float x) {
    unsigned r;
    asm("cvt.rna.tf32.f32 %0, %1;" : "=r"(r) : "f"(x));
    return r;
}
__device__ __forceinline__ float f2tf_f(float x) {
    return __uint_as_float(f2tf(x));
}
__device__ __forceinline__ void mma_tf32(float* d, const unsigned* a,
                                         unsigned b0, unsigned b1) {
    asm volatile(
        "mma.sync.aligned.m16n8k8.row.col.f32.tf32.tf32.f32 "
        "{%0,%1,%2,%3}, {%4,%5,%6,%7}, {%8,%9}, {%0,%1,%2,%3};\n"
        : "+f"(d[0]), "+f"(d[1]), "+f"(d[2]), "+f"(d[3])
        : "r"(a[0]), "r"(a[1]), "r"(a[2]), "r"(a[3]), "r"(b0), "r"(b1));
}
__device__ __forceinline__ void ldsm_x4(uint4& d, unsigned addr) {
    asm volatile("ldmatrix.sync.aligned.m8n8.x4.shared.b16 {%0,%1,%2,%3}, [%4];"
                 : "=r"(d.x), "=r"(d.y), "=r"(d.z), "=r"(d.w) : "r"(addr));
}
#define CP16(dst, src) \
    asm volatile("cp.async.cg.shared.global [%0], [%1], 16;" :: "r"(dst), "l"(src))
#define CP_COMMIT() asm volatile("cp.async.commit_group;")
#define CP_WAIT(n)  asm volatile("cp.async.wait_group %0;" :: "n"(n))

// ---------------------------------------------------------------------------
// Pre-round fp32 -> tf32 bit pattern (elementwise, float4)
// ---------------------------------------------------------------------------
__global__ void cvt_tf32_kernel(const float* __restrict__ src,
                                float* __restrict__ dst, int n4)
{
    int i = blockIdx.x * blockDim.x + threadIdx.x;
    if (i < n4) {
        float4 v = ((const float4*)src)[i];
        uint4 u;
        u.x = f2tf(v.x); u.y = f2tf(v.y); u.z = f2tf(v.z); u.w = f2tf(v.w);
        ((uint4*)dst)[i] = u;
    }
}

// ---------------------------------------------------------------------------
// tf32 tensor-core GEMM: C = A[4032,1536] @ B[1536,1536] + bias
// CTA 128x128, K-step 32, 3-stage cp.async pipeline, ldmatrix A-frags.
// As: [m(128)][k(32)+4pad] stride 36 ; Bs: [k(32)][n(128)+8pad] stride 136
// ---------------------------------------------------------------------------
#define AS_W 36
#define BS_W 136
#define A_WORDS (128 * AS_W)
#define B_WORDS (32 * BS_W)
#define BUF_WORDS (A_WORDS + B_WORDS)
#define N_STAGE 3
#define GEMM_SMEM_BYTES (N_STAGE * BUF_WORDS * 4)   // 107,520

__device__ __forceinline__ void gemm_tc(const float* __restrict__ A,
                                        const float* __restrict__ B,
                                        const float* __restrict__ bias,
                                        float* __restrict__ C,
                                        int row0, int col0,
                                        unsigned* smu, bool round_out)
{
    const int tid  = threadIdx.x;
    const int lane = tid & 31;
    const int warp = tid >> 5;
    const int wm = warp >> 2;
    const int wn = warp & 3;
    const int r  = lane >> 2;
    const int c  = lane & 3;

    const int a_lrow  = lane & 15;
    const int a_lhalf = (lane >> 4) << 2;

    const int st_arow = tid >> 3;
    const int st_ak   = (tid & 7) << 2;
    const int st_bk   = tid >> 5;
    const int st_bn   = (tid & 31) << 2;

    float acc[4][4][4];
#pragma unroll
    for (int mt = 0; mt < 4; mt++)
#pragma unroll
        for (int nt = 0; nt < 4; nt++)
#pragma unroll
            for (int i = 0; i < 4; i++) acc[mt][nt][i] = 0.f;

    auto issue_tile = [&](int kb, int buf) {
        unsigned abase = (unsigned)__cvta_generic_to_shared(&smu[buf * BUF_WORDS]);
        unsigned bbase = (unsigned)__cvta_generic_to_shared(&smu[buf * BUF_WORDS + A_WORDS]);
#pragma unroll
        for (int p = 0; p < 4; p++) {
            int row  = st_arow + p * 32;
            int grow = row0 + row;
            grow = (grow < S_TOK) ? grow : (S_TOK - 1);
            CP16(abase + (unsigned)(row * AS_W + st_ak) * 4,
                 &A[(size_t)grow * DIMC + kb + st_ak]);
            int kr = st_bk + p * 8;
            CP16(bbase + (unsigned)(kr * BS_W + st_bn) * 4,
                 &B[(size_t)(kb + kr) * DIMC + col0 + st_bn]);
        }
    };

    auto compute = [&](int buf) {
        const unsigned* As = smu + buf * BUF_WORDS;
        const unsigned* Bs = smu + buf * BUF_WORDS + A_WORDS;
#pragma unroll
        for (int kk = 0; kk < 4; kk++) {
            uint4 a[4];
#pragma unroll
            for (int mt = 0; mt < 4; mt++) {
                unsigned addr = (unsigned)__cvta_generic_to_shared(
                    &As[(wm * 64 + mt * 16 + a_lrow) * AS_W + kk * 8 + a_lhalf]);
                ldsm_x4(a[mt], addr);
            }
            uint2 b[4];
#pragma unroll
            for (int nt = 0; nt < 4; nt++) {
                int nb = wn * 32 + nt * 8 + r;
                b[nt].x = Bs[(kk * 8 + c) * BS_W + nb];
                b[nt].y = Bs[(kk * 8 + c + 4) * BS_W + nb];
            }
#pragma unroll
            for (int mt = 0; mt < 4; mt++)
#pragma unroll
                for (int nt = 0; nt < 4; nt++)
                    mma_tf32(acc[mt][nt], (const unsigned*)&a[mt], b[nt].x, b[nt].y);
        }
    };

    const int NKB = DIMC / 32;
    issue_tile(0, 0);
    CP_COMMIT();
    issue_tile(32, 1);
    CP_COMMIT();
    for (int kb = 0; kb < NKB; kb++) {
        if (kb < NKB - 1) { CP_WAIT(1); } else { CP_WAIT(0); }
        __syncthreads();
        if (kb + 2 < NKB) {
            issue_tile((kb + 2) * 32, (kb + 2) % N_STAGE);
            CP_COMMIT();
        }
        compute(kb % N_STAGE);
    }

#pragma unroll
    for (int mt = 0; mt < 4; mt++) {
        int row_a = row0 + wm * 64 + mt * 16 + r;
        int row_b = row_a + 8;
#pragma unroll
        for (int nt = 0; nt < 4; nt++) {
            int col = col0 + wn * 32 + nt * 8 + 2 * c;
            float b0 = bias[col], b1 = bias[col + 1];
            float v0 = acc[mt][nt][0] + b0, v1 = acc[mt][nt][1] + b1;
            float v2 = acc[mt][nt][2] + b0, v3 = acc[mt][nt][3] + b1;
            if (round_out) {
                v0 = f2tf_f(v0); v1 = f2tf_f(v1);
                v2 = f2tf_f(v2); v3 = f2tf_f(v3);
            }
            if (row_a < S_TOK)
                *(float2*)&C[(size_t)row_a * DIMC + col] = make_float2(v0, v1);
            if (row_b < S_TOK)
                *(float2*)&C[(size_t)row_b * DIMC + col] = make_float2(v2, v3);
        }
    }
}

__global__ void __launch_bounds__(256)
qkv_gemm(const float* __restrict__ bq, const float* __restrict__ bk,
         const float* __restrict__ bv)
{
    extern __shared__ unsigned smu[];
    int z = blockIdx.z;
    const float* B    = (z == 0) ? g_wq : ((z == 1) ? g_wk : g_wv);
    const float* bias = (z == 0) ? bq : ((z == 1) ? bk : bv);
    float* C          = (z == 0) ? g_q : ((z == 1) ? g_k : g_v);
    gemm_tc(g_x, B, bias, C, blockIdx.y * 128, blockIdx.x * 128, smu, z == 2);
}

__global__ void __launch_bounds__(256)
out_gemm(const float* __restrict__ bo, float* __restrict__ out)
{
    extern __shared__ unsigned smu[];
    gemm_tc(g_attn, g_wo, bo, out, blockIdx.y * 128, blockIdx.x * 128, smu, false);
}

// ---------------------------------------------------------------------------
// Fused RMSNorm (full DIM) + 3D RoPE, in-place on g_q / g_k; tf32-rounded out.
// ---------------------------------------------------------------------------
__global__ void norm_rope_kernel(const float* __restrict__ freqs,
                                 const float* __restrict__ gq,
                                 const float* __restrict__ gk)
{
    int s = blockIdx.x;
    int tid = threadIdx.x;
    float* qrow = g_q + (size_t)s * DIMC;
    float* krow = g_k + (size_t)s * DIMC;

    float2 qv[3], kv[3];
    float sq = 0.f, sk = 0.f;
#pragma unroll
    for (int p = 0; p < 3; p++) {
        int pr = tid + p * 256;
        qv[p] = *(const float2*)&qrow[2 * pr];
        kv[p] = *(const float2*)&krow[2 * pr];
        sq += qv[p].x * qv[p].x + qv[p].y * qv[p].y;
        sk += kv[p].x * kv[p].x + kv[p].y * kv[p].y;
    }
    __shared__ float red[2][8];
#pragma unroll
    for (int o = 16; o > 0; o >>= 1) {
        sq += __shfl_down_sync(0xffffffffu, sq, o);
        sk += __shfl_down_sync(0xffffffffu, sk, o);
    }
    int warp = tid >> 5;
    if ((tid & 31) == 0) { red[0][warp] = sq; red[1][warp] = sk; }
    __syncthreads();
    sq = 0.f; sk = 0.f;
#pragma unroll
    for (int w = 0; w < 8; w++) { sq += red[0][w]; sk += red[1][w]; }
    float rq = rsqrtf(sq * (1.f / DIMC) + 1e-6f);
    float rk = rsqrtf(sk * (1.f / DIMC) + 1e-6f);

    int f = s / FRAME;
    int rem = s % FRAME;
    int hh = rem / 28;
    int ww = rem % 28;
#pragma unroll
    for (int p = 0; p < 3; p++) {
        int pr = tid + p * 256;
        int rot = pr & 63;
        float a;
        if (rot < 22)       a = freqs[f  * ROTC + rot];
        else if (rot < 43)  a = freqs[hh * ROTC + rot];
        else                a = freqs[ww * ROTC + rot];
        float cc = cosf(a), sn = sinf(a);
        float q0 = qv[p].x * rq * gq[2 * pr];
        float q1 = qv[p].y * rq * gq[2 * pr + 1];
        float k0 = kv[p].x * rk * gk[2 * pr];
        float k1 = kv[p].y * rk * gk[2 * pr + 1];
        *(float2*)&qrow[2 * pr] =
            make_float2(f2tf_f(q0 * cc - q1 * sn), f2tf_f(q0 * sn + q1 * cc));
        *(float2*)&krow[2 * pr] =
            make_float2(f2tf_f(k0 * cc - k1 * sn), f2tf_f(k0 * sn + k1 * cc));
    }
}

// ---------------------------------------------------------------------------
// Frame-causal flash attention, tf32 tensor cores, cp.async phase-split
// prefetch (K(kt+1) hidden under softmax+PV; V(kt+1) hidden under next S).
// Block = (64 q-rows, head), 128 threads. Longest q-tiles launch first.
// ---------------------------------------------------------------------------
#define QS_W 132
#define KS_W 132
#define VS_W 136
#define QS_OFF 0
#define KS_OFF (64 * QS_W)
#define VS_OFF (KS_OFF + 64 * KS_W)
#define ATTN_SMEM_U (VS_OFF + 64 * VS_W)   // 25,600 words = 102,400 B
#define PS_STRIDE 68

__global__ void __launch_bounds__(128)
attn_kernel()
{
    extern __shared__ unsigned asm_u[];
    unsigned* Qs = asm_u + QS_OFF;
    unsigned* Ps = asm_u + QS_OFF;    // alias (Qs dead after frag load)
    unsigned* Ks = asm_u + KS_OFF;
    unsigned* Vs = asm_u + VS_OFF;

    const int tid  = threadIdx.x;
    const int lane = tid & 31;
    const int w    = tid >> 5;
    const int r    = lane >> 2;
    const int c    = lane & 3;
    const int w16  = w * 16;

    const int qb   = 62 - blockIdx.x;          // longest blocks first
    const int row0 = qb * 64;
    const int h    = blockIdx.y;
    const int ktiles = (row0 / FRAME + 1) * (FRAME / 64);
    const float scale = 0.08838834764831845f;

    // staging coords (shared by K and V issue loops)
    const int st_r = tid >> 3;              // 0..15 base (x4 passes)
    const int st_c = (tid & 7) << 2;        // 0,4,..,28 -> cc = st_c..st_c+3? no:
    // we stage 64 rows x 32 words: idx = tid + it*128; rr = idx>>5; cc=(idx&31)<<2

    auto issue_k = [&](int krow0) {
        unsigned kbase = (unsigned)__cvta_generic_to_shared(Ks);
#pragma unroll
        for (int it = 0; it < 16; it++) {
            int idx = tid + it * 128;
            int rr = idx >> 5;
            int cc = (idx & 31) << 2;
            CP16(kbase + (unsigned)(rr * KS_W + cc) * 4,
                 &g_k[(size_t)(krow0 + rr) * DIMC + h * HDIM + cc]);
        }
        CP_COMMIT();
    };
    auto issue_v = [&](int krow0) {
        unsigned vbase = (unsigned)__cvta_generic_to_shared(Vs);
#pragma unroll
        for (int it = 0; it < 16; it++) {
            int idx = tid + it * 128;
            int rr = idx >> 5;
            int cc = (idx & 31) << 2;
            CP16(vbase + (unsigned)(rr * VS_W + cc) * 4,
                 &g_v[(size_t)(krow0 + rr) * DIMC + h * HDIM + cc]);
        }
        CP_COMMIT();
    };

    // Kick off K(0), V(0) before Q staging (maximum overlap)
    issue_k(0);
    issue_v(0);

    // Stage Q (raw copy, already tf32 bits)
#pragma unroll
    for (int it = 0; it < 16; it++) {
        int idx = tid + it * 128;
        int rr = idx >> 5;
        int cc = (idx & 31) << 2;
        *(uint4*)&Qs[rr * QS_W + cc] =
            *(const uint4*)&g_q[(size_t)(row0 + rr) * DIMC + h * HDIM + cc];
    }
    __syncthreads();

    unsigned qa[16][4];
#pragma unroll
    for (int dt = 0; dt < 16; dt++) {
        qa[dt][0] = Qs[(w16 + r) * QS_W + dt * 8 + c];
        qa[dt][1] = Qs[(w16 + r + 8) * QS_W + dt * 8 + c];
        qa[dt][2] = Qs[(w16 + r) * QS_W + dt * 8 + c + 4];
        qa[dt][3] = Qs[(w16 + r + 8) * QS_W + dt * 8 + c + 4];
    }

    float O[16][4];
#pragma unroll
    for (int nt = 0; nt < 16; nt++)
#pragma unroll
        for (int i = 0; i < 4; i++) O[nt][i] = 0.f;
    float m0 = -1e30f, m1 = -1e30f, l0 = 0.f, l1 = 0.f;

    for (int kt = 0; kt < ktiles; kt++) {
        // Wait K(kt) (oldest pending group); V(kt) may still be in flight
        CP_WAIT(1);
        __syncthreads();

        // S = Q K^T
        float S[8][4];
#pragma unroll
        for (int nt = 0; nt < 8; nt++)
#pragma unroll
            for (int i = 0; i < 4; i++) S[nt][i] = 0.f;
#pragma unroll
        for (int dt = 0; dt < 16; dt++) {
#pragma unroll
            for (int nt = 0; nt < 8; nt++) {
                unsigned b0 = Ks[(nt * 8 + r) * KS_W + dt * 8 + c];
                unsigned b1 = Ks[(nt * 8 + r) * KS_W + dt * 8 + c + 4];
                mma_tf32(S[nt], qa[dt], b0, b1);
            }
        }
        __syncthreads();               // all warps done reading Ks
        if (kt + 1 < ktiles) issue_k((kt + 1) * 64);   // overlaps softmax+PV

        // Online softmax
        float mx0 = -1e30f, mx1 = -1e30f;
#pragma unroll
        for (int nt = 0; nt < 8; nt++) {
            mx0 = fmaxf(mx0, fmaxf(S[nt][0], S[nt][1]));
            mx1 = fmaxf(mx1, fmaxf(S[nt][2], S[nt][3]));
        }
        mx0 = fmaxf(mx0, __shfl_xor_sync(0xffffffffu, mx0, 1));
        mx0 = fmaxf(mx0, __shfl_xor_sync(0xffffffffu, mx0, 2));
        mx1 = fmaxf(mx1, __shfl_xor_sync(0xffffffffu, mx1, 1));
        mx1 = fmaxf(mx1, __shfl_xor_sync(0xffffffffu, mx1, 2));
        float mn0 = fmaxf(m0, mx0), mn1 = fmaxf(m1, mx1);
        float fac0 = __expf((m0 - mn0) * scale);
        float fac1 = __expf((m1 - mn1) * scale);

        float sum0 = 0.f, sum1 = 0.f;
#pragma unroll
        for (int nt = 0; nt < 8; nt++) {
            float p00 = __expf((S[nt][0] - mn0) * scale);
            float p01 = __expf((S[nt][1] - mn0) * scale);
            float p10 = __expf((S[nt][2] - mn1) * scale);
            float p11 = __expf((S[nt][3] - mn1) * scale);
            sum0 += p00 + p01;
            sum1 += p10 + p11;
            *(uint2*)&Ps[(w16 + r) * PS_STRIDE + nt * 8 + 2 * c] =
                make_uint2(f2tf(p00), f2tf(p01));
            *(uint2*)&Ps[(w16 + r + 8) * PS_STRIDE + nt * 8 + 2 * c] =
                make_uint2(f2tf(p10), f2tf(p11));
        }
        sum0 += __shfl_xor_sync(0xffffffffu, sum0, 1);
        sum0 += __shfl_xor_sync(0xffffffffu, sum0, 2);
        sum1 += __shfl_xor_sync(0xffffffffu, sum1, 1);
        sum1 += __shfl_xor_sync(0xffffffffu, sum1, 2);
        l0 = l0 * fac0 + sum0;
        l1 = l1 * fac1 + sum1;
        m0 = mn0; m1 = mn1;

#pragma unroll
        for (int nt = 0; nt < 16; nt++) {
            O[nt][0] *= fac0; O[nt][1] *= fac0;
            O[nt][2] *= fac1; O[nt][3] *= fac1;
        }

        // Wait V(kt) (now oldest pending: K(kt+1) is newer)
        if (kt + 1 < ktiles) { CP_WAIT(1); } else { CP_WAIT(0); }
        __syncthreads();               // V visible to all; Ps visible too

        // O += P V
#pragma unroll
        for (int k8 = 0; k8 < 8; k8++) {
            unsigned pa[4];
            pa[0] = Ps[(w16 + r) * PS_STRIDE + k8 * 8 + c];
            pa[1] = Ps[(w16 + r + 8) * PS_STRIDE + k8 * 8 + c];
            pa[2] = Ps[(w16 + r) * PS_STRIDE + k8 * 8 + c + 4];
            pa[3] = Ps[(w16 + r + 8) * PS_STRIDE + k8 * 8 + c + 4];
#pragma unroll
            for (int nt = 0; nt < 16; nt++) {
                unsigned b0 = Vs[(k8 * 8 + c) * VS_W + nt * 8 + r];
                unsigned b1 = Vs[(k8 * 8 + c + 4) * VS_W + nt * 8 + r];
                mma_tf32(O[nt], pa, b0, b1);
            }
        }
        __syncthreads();               // all warps done reading Vs (and Ps)
        if (kt + 1 < ktiles) issue_v((kt + 1) * 64);   // overlaps next S
    }

    // Epilogue: normalize, tf32-round (out_gemm consumes raw bits)
    float inv0 = 1.f / l0, inv1 = 1.f / l1;
    int row_a = row0 + w16 + r;
    int row_b = row_a + 8;
#pragma unroll
    for (int nt = 0; nt < 16; nt++) {
        int col = h * HDIM + nt * 8 + 2 * c;
        *(float2*)&g_attn[(size_t)row_a * DIMC + col] =
            make_float2(f2tf_f(O[nt][0] * inv0), f2tf_f(O[nt][1] * inv0));
        *(float2*)&g_attn[(size_t)row_b * DIMC + col] =
            make_float2(f2tf_f(O[nt][2] * inv1), f2tf_f(O[nt][3] * inv1));
    }
}

// ---------------------------------------------------------------------------
extern "C" void kernel_launch(void* const* d_in, const int* in_sizes, int n_in,
                              void* d_out, int out_size)
{
    (void)in_sizes; (void)n_in; (void)out_size;
    const float* x     = (const float*)d_in[0];
    const float* freqs = (const float*)d_in[3];
    const float* Wq    = (const float*)d_in[4];
    const float* bq    = (const float*)d_in[5];
    const float* Wk    = (const float*)d_in[6];
    const float* bk    = (const float*)d_in[7];
    const float* Wv    = (const float*)d_in[8];
    const float* bv    = (const float*)d_in[9];
    const float* Wo    = (const float*)d_in[10];
    const float* bo    = (const float*)d_in[11];
    const float* gq    = (const float*)d_in[12];
    const float* gk    = (const float*)d_in[13];
    float* out = (float*)d_out;

    const int gemm_smem = GEMM_SMEM_BYTES;
    const int attn_smem = ATTN_SMEM_U * 4;
    cudaFuncSetAttribute(qkv_gemm,
                         cudaFuncAttributeMaxDynamicSharedMemorySize, gemm_smem);
    cudaFuncSetAttribute(out_gemm,
                         cudaFuncAttributeMaxDynamicSharedMemorySize, gemm_smem);
    cudaFuncSetAttribute(attn_kernel,
                         cudaFuncAttributeMaxDynamicSharedMemorySize, attn_smem);

    float* dxp; float* dwq; float* dwk; float* dwv; float* dwo;
    cudaGetSymbolAddress((void**)&dxp, g_x);
    cudaGetSymbolAddress((void**)&dwq, g_wq);
    cudaGetSymbolAddress((void**)&dwk, g_wk);
    cudaGetSymbolAddress((void**)&dwv, g_wv);
    cudaGetSymbolAddress((void**)&dwo, g_wo);
    const int NX4 = S_TOK * DIMC / 4;
    const int NW4 = DIMC * DIMC / 4;
    cvt_tf32_kernel<<<(NX4 + 255) / 256, 256>>>(x,  dxp, NX4);
    cvt_tf32_kernel<<<(NW4 + 255) / 256, 256>>>(Wq, dwq, NW4);
    cvt_tf32_kernel<<<(NW4 + 255) / 256, 256>>>(Wk, dwk, NW4);
    cvt_tf32_kernel<<<(NW4 + 255) / 256, 256>>>(Wv, dwv, NW4);
    cvt_tf32_kernel<<<(NW4 + 255) / 256, 256>>>(Wo, dwo, NW4);

    qkv_gemm<<<dim3(12, 32, 3), 256, gemm_smem>>>(bq, bk, bv);
    norm_rope_kernel<<<S_TOK, 256>>>(freqs, gq, gk);
    attn_kernel<<<dim3(63, 12), 128, attn_smem>>>();
    out_gemm<<<dim3(12, 32), 256, gemm_smem>>>(bo, out);
}